// round 2
// baseline (speedup 1.0000x reference)
#include <cuda_runtime.h>

// GCN: embedding mean-pool -> GraphConv(128->128, relu) -> GraphConv(128->40)
// N=50000 nodes, E=800000 edges, F=128 feats, SEQ=20 tokens, CLS=40 classes.
//
// Pipeline (all norms folded into epilogues):
//   bufA = meanpool(emb[features]) * rsqrt(out_deg)          (k_embed)
//   bufB = 0; bufB[dst] += bufA[src]                          (k_zeroB, k_spmm)
//   bufA = relu((bufB * rsqrt(in_deg)) @ W1 + b1) * rsqrt(out_deg)   (k_gemm1)
//   bufB = 0; bufB[dst] += bufA[src]                          (k_zeroB, k_spmm)
//   out  = (bufB * rsqrt(in_deg)) @ W2 + b2                   (k_gemm2)

#define NN  50000
#define NE  800000
#define FD  128
#define SEQ 20
#define CLS 40

static __device__ float g_bufA[(size_t)NN * FD];
static __device__ float g_bufB[(size_t)NN * FD];
static __device__ int   g_odeg[NN];
static __device__ int   g_ideg[NN];
static __device__ float g_rso[NN];
static __device__ float g_rsi[NN];

__global__ __launch_bounds__(256) void k_zero_deg() {
    int i = blockIdx.x * 256 + threadIdx.x;
    if (i < NN) { g_odeg[i] = 0; g_ideg[i] = 0; }
}

__global__ __launch_bounds__(256) void k_deg(const int* __restrict__ src,
                                             const int* __restrict__ dst) {
    int e = blockIdx.x * 256 + threadIdx.x;
    if (e < NE) {
        atomicAdd(&g_odeg[src[e]], 1);
        atomicAdd(&g_ideg[dst[e]], 1);
    }
}

__global__ __launch_bounds__(256) void k_rs() {
    int i = blockIdx.x * 256 + threadIdx.x;
    if (i < NN) {
        g_rso[i] = rsqrtf((float)max(g_odeg[i], 1));
        g_rsi[i] = rsqrtf((float)max(g_ideg[i], 1));
    }
}

// exactly NN*FD/4 = 1,600,000 float4 stores; grid = 6250 x 256
__global__ __launch_bounds__(256) void k_zeroB() {
    int i = blockIdx.x * 256 + threadIdx.x;
    ((float4*)g_bufB)[i] = make_float4(0.f, 0.f, 0.f, 0.f);
}

// warp per node: mean-pool 20 embedding rows, fold 1/count and rsqrt(out_deg)
__global__ __launch_bounds__(256) void k_embed(const int* __restrict__ feat,
                                               const float* __restrict__ emb) {
    int w    = (blockIdx.x * 256 + threadIdx.x) >> 5;
    int lane = threadIdx.x & 31;
    if (w >= NN) return;
    int tok = 0;
    if (lane < SEQ) tok = feat[w * SEQ + lane];
    unsigned nzm = __ballot_sync(0xffffffffu, (lane < SEQ) && (tok != 0));
    float inv_cnt = 1.0f / (float)max(__popc(nzm), 1);
    float4 acc = make_float4(0.f, 0.f, 0.f, 0.f);
#pragma unroll
    for (int t = 0; t < SEQ; ++t) {
        int tk = __shfl_sync(0xffffffffu, tok, t);
        float4 v = ((const float4*)(emb + (long)tk * FD))[lane];
        acc.x += v.x; acc.y += v.y; acc.z += v.z; acc.w += v.w;
    }
    float s = g_rso[w] * inv_cnt;
    ((float4*)(g_bufA + (long)w * FD))[lane] =
        make_float4(acc.x * s, acc.y * s, acc.z * s, acc.w * s);
}

// warp per edge: gather 512B row from bufA[src], vector-reduce into bufB[dst]
__global__ __launch_bounds__(256) void k_spmm(const int* __restrict__ src,
                                              const int* __restrict__ dst) {
    int w    = (blockIdx.x * 256 + threadIdx.x) >> 5;
    int lane = threadIdx.x & 31;
    if (w >= NE) return;
    int s = src[w];
    int d = dst[w];
    float4 v = ((const float4*)(g_bufA + (long)s * FD))[lane];
    float* p = g_bufB + (long)d * FD + lane * 4;
    asm volatile("red.global.add.v4.f32 [%0], {%1, %2, %3, %4};"
                 :: "l"(p), "f"(v.x), "f"(v.y), "f"(v.z), "f"(v.w)
                 : "memory");
}

// grid (gx, 2): blockIdx.y selects 64-col half of W1 (32KB smem slice).
// warp per row; x row held in registers, broadcast via shfl; fold rsi, bias,
// relu, rso in the epilogue. Writes bufA.
__global__ __launch_bounds__(256) void k_gemm1(const float* __restrict__ W1,
                                               const float* __restrict__ b1) {
    __shared__ float sW[FD * 64];
    int cb = blockIdx.y * 64;
    for (int i = threadIdx.x; i < FD * 64; i += 256)
        sW[i] = W1[(i >> 6) * FD + cb + (i & 63)];
    __syncthreads();
    int warp = threadIdx.x >> 5, lane = threadIdx.x & 31;
    float2 bias = ((const float2*)(b1 + cb))[lane];
    for (int r = blockIdx.x * 8 + warp; r < NN; r += gridDim.x * 8) {
        float rin = g_rsi[r];
        float4 x = ((const float4*)(g_bufB + (long)r * FD))[lane];
        x.x *= rin; x.y *= rin; x.z *= rin; x.w *= rin;
        float a0 = 0.f, a1 = 0.f;
#pragma unroll
        for (int kb = 0; kb < 32; ++kb) {
            float x0 = __shfl_sync(0xffffffffu, x.x, kb);
            float x1 = __shfl_sync(0xffffffffu, x.y, kb);
            float x2 = __shfl_sync(0xffffffffu, x.z, kb);
            float x3 = __shfl_sync(0xffffffffu, x.w, kb);
            const float* wp = &sW[(4 * kb) * 64 + 2 * lane];
            float2 v0 = *(const float2*)(wp);
            float2 v1 = *(const float2*)(wp + 64);
            float2 v2 = *(const float2*)(wp + 128);
            float2 v3 = *(const float2*)(wp + 192);
            a0 = fmaf(x0, v0.x, a0); a1 = fmaf(x0, v0.y, a1);
            a0 = fmaf(x1, v1.x, a0); a1 = fmaf(x1, v1.y, a1);
            a0 = fmaf(x2, v2.x, a0); a1 = fmaf(x2, v2.y, a1);
            a0 = fmaf(x3, v3.x, a0); a1 = fmaf(x3, v3.y, a1);
        }
        float rout = g_rso[r];
        float o0 = fmaxf(a0 + bias.x, 0.f) * rout;
        float o1 = fmaxf(a1 + bias.y, 0.f) * rout;
        *(float2*)(g_bufA + (long)r * FD + cb + 2 * lane) = make_float2(o0, o1);
    }
}

// W2 padded to 64 cols in smem (cols 40..63 = 0) so both per-lane column
// reads stay in-bounds without divergence. lane owns cols {lane, lane+32}.
__global__ __launch_bounds__(256) void k_gemm2(const float* __restrict__ W2,
                                               const float* __restrict__ b2,
                                               float* __restrict__ out) {
    __shared__ float sW[FD * 64];
    for (int i = threadIdx.x; i < FD * 64; i += 256) {
        int k = i >> 6, c = i & 63;
        sW[i] = (c < CLS) ? W2[k * CLS + c] : 0.f;
    }
    __syncthreads();
    int warp = threadIdx.x >> 5, lane = threadIdx.x & 31;
    float bias0 = b2[lane];                       // lane<32 < CLS=40, valid
    float bias1 = (lane < 8) ? b2[32 + lane] : 0.f;
    for (int r = blockIdx.x * 8 + warp; r < NN; r += gridDim.x * 8) {
        float rin = g_rsi[r];
        float4 x = ((const float4*)(g_bufB + (long)r * FD))[lane];
        x.x *= rin; x.y *= rin; x.z *= rin; x.w *= rin;
        float a0 = 0.f, a1 = 0.f;
#pragma unroll
        for (int kb = 0; kb < 32; ++kb) {
            float x0 = __shfl_sync(0xffffffffu, x.x, kb);
            float x1 = __shfl_sync(0xffffffffu, x.y, kb);
            float x2 = __shfl_sync(0xffffffffu, x.z, kb);
            float x3 = __shfl_sync(0xffffffffu, x.w, kb);
            const float* wp = &sW[(4 * kb) * 64];
            a0 = fmaf(x0, wp[lane],        a0); a1 = fmaf(x0, wp[32 + lane],  a1);
            a0 = fmaf(x1, wp[64 + lane],   a0); a1 = fmaf(x1, wp[96 + lane],  a1);
            a0 = fmaf(x2, wp[128 + lane],  a0); a1 = fmaf(x2, wp[160 + lane], a1);
            a0 = fmaf(x3, wp[192 + lane],  a0); a1 = fmaf(x3, wp[224 + lane], a1);
        }
        float* orow = out + (long)r * CLS;
        orow[lane] = a0 + bias0;
        if (lane < 8) orow[32 + lane] = a1 + bias1;
    }
}

extern "C" void kernel_launch(void* const* d_in, const int* in_sizes, int n_in,
                              void* d_out, int out_size) {
    const int*   feat = (const int*)  d_in[0];
    const int*   src  = (const int*)  d_in[1];
    const int*   dst  = (const int*)  d_in[2];
    const float* emb  = (const float*)d_in[3];
    const float* W1   = (const float*)d_in[4];
    const float* b1   = (const float*)d_in[5];
    const float* W2   = (const float*)d_in[6];
    const float* b2   = (const float*)d_in[7];
    float* out = (float*)d_out;

    k_zero_deg<<<(NN + 255) / 256, 256>>>();
    k_deg<<<(NE + 255) / 256, 256>>>(src, dst);
    k_rs<<<(NN + 255) / 256, 256>>>();
    k_embed<<<NN / 8, 256>>>(feat, emb);          // 6250 blocks, warp/node
    k_zeroB<<<NN * FD / 4 / 256, 256>>>();        // 6250 blocks
    k_spmm<<<NE / 8, 256>>>(src, dst);            // 100000 blocks, warp/edge
    k_gemm1<<<dim3(625, 2), 256>>>(W1, b1);
    k_zeroB<<<NN * FD / 4 / 256, 256>>>();
    k_spmm<<<NE / 8, 256>>>(src, dst);
    k_gemm2<<<625, 256>>>(W2, b2, out);
}

// round 3
// speedup vs baseline: 2.1823x; 2.1823x over previous
#include <cuda_runtime.h>

// GCN: embedding mean-pool -> GraphConv(128->128, relu) -> GraphConv(128->40)
// Pull-based (CSR by dst, built on the fly) — no float atomics, no zeroing.
//
//   bufA = rso * meanpool(emb[features])                       (k_embed)
//   CSR: off/csr_src from (src,dst)                            (scan + fill)
//   bufB = rso * relu( (rsi * sum_{e->d} bufA[src]) @ W1 + b1) (k_layer1, fused)
//   y    = bufB @ W2                                           (k_gemm2y)  [S(h)W = (Sh)W reorder]
//   out  = rsi * sum_{e->d} y[src] + b2                        (k_spmm2)

#define NN  50000
#define NE  800000
#define FD  128
#define SEQ 20
#define CLS 40
#define NB  ((NN + 255) / 256)   // 196 scan blocks

static __device__ float g_bufA[(size_t)NN * FD];
static __device__ float g_bufB[(size_t)NN * FD];
static __device__ float g_y[(size_t)NN * CLS];
static __device__ int   g_odeg[NN];
static __device__ int   g_ideg[NN];
static __device__ float g_rso[NN];
static __device__ float g_rsi[NN];
static __device__ int   g_off[NN + 1];
static __device__ int   g_cur[NN];
static __device__ int   g_csr[NE];
static __device__ int   g_btot[256];
static __device__ int   g_bscan[256];

__global__ __launch_bounds__(256) void k_zero() {
    int i = blockIdx.x * 256 + threadIdx.x;
    if (i < NN) { g_odeg[i] = 0; g_ideg[i] = 0; g_cur[i] = 0; }
}

__global__ __launch_bounds__(256) void k_deg(const int* __restrict__ src,
                                             const int* __restrict__ dst) {
    int e = blockIdx.x * 256 + threadIdx.x;
    if (e < NE) {
        atomicAdd(&g_odeg[src[e]], 1);
        atomicAdd(&g_ideg[dst[e]], 1);
    }
}

__global__ __launch_bounds__(256) void k_rs() {
    int i = blockIdx.x * 256 + threadIdx.x;
    if (i < NN) {
        g_rso[i] = rsqrtf((float)max(g_odeg[i], 1));
        g_rsi[i] = rsqrtf((float)max(g_ideg[i], 1));
    }
}

// ---- 3-phase exclusive scan of g_ideg -> g_off ----
__global__ __launch_bounds__(256) void k_scanA() {
    __shared__ int s[256];
    int tid = threadIdx.x;
    int i = blockIdx.x * 256 + tid;
    int v = (i < NN) ? g_ideg[i] : 0;
    s[tid] = v; __syncthreads();
#pragma unroll
    for (int st = 1; st < 256; st <<= 1) {
        int t = (tid >= st) ? s[tid - st] : 0;
        __syncthreads();
        s[tid] += t;
        __syncthreads();
    }
    if (i < NN) g_off[i] = s[tid] - v;            // exclusive within block
    if (tid == 255) g_btot[blockIdx.x] = s[255];
}

__global__ __launch_bounds__(256) void k_scanB() {
    __shared__ int s[256];
    int tid = threadIdx.x;
    int v = (tid < NB) ? g_btot[tid] : 0;
    s[tid] = v; __syncthreads();
#pragma unroll
    for (int st = 1; st < 256; st <<= 1) {
        int t = (tid >= st) ? s[tid - st] : 0;
        __syncthreads();
        s[tid] += t;
        __syncthreads();
    }
    g_bscan[tid] = s[tid] - v;                    // exclusive across blocks
}

__global__ __launch_bounds__(256) void k_scanC() {
    int i = blockIdx.x * 256 + threadIdx.x;
    if (i < NN) g_off[i] += g_bscan[i >> 8];
    if (i == 0) g_off[NN] = NE;
}

__global__ __launch_bounds__(256) void k_fill(const int* __restrict__ src,
                                              const int* __restrict__ dst) {
    int e = blockIdx.x * 256 + threadIdx.x;
    if (e < NE) {
        int d = dst[e];
        int p = g_off[d] + atomicAdd(&g_cur[d], 1);
        g_csr[p] = src[e];
    }
}

// warp per node: mean-pool 20 embedding rows, fold 1/count and rsqrt(out_deg)
__global__ __launch_bounds__(256) void k_embed(const int* __restrict__ feat,
                                               const float* __restrict__ emb) {
    int w    = (blockIdx.x * 256 + threadIdx.x) >> 5;
    int lane = threadIdx.x & 31;
    if (w >= NN) return;
    int tok = 0;
    if (lane < SEQ) tok = feat[w * SEQ + lane];
    unsigned nzm = __ballot_sync(0xffffffffu, (lane < SEQ) && (tok != 0));
    float inv_cnt = 1.0f / (float)max(__popc(nzm), 1);
    float4 acc = make_float4(0.f, 0.f, 0.f, 0.f);
#pragma unroll
    for (int t = 0; t < SEQ; ++t) {
        int tk = __shfl_sync(0xffffffffu, tok, t);
        float4 v = ((const float4*)(emb + (long)tk * FD))[lane];
        acc.x += v.x; acc.y += v.y; acc.z += v.z; acc.w += v.w;
    }
    float s = g_rso[w] * inv_cnt;
    ((float4*)(g_bufA + (long)w * FD))[lane] =
        make_float4(acc.x * s, acc.y * s, acc.z * s, acc.w * s);
}

// Fused layer 1: warp per dst node. CSR gather-accumulate bufA rows into
// registers, scale by rsi, GEMM vs W1 (full 64KB in dynamic smem),
// relu + bias + rso, write bufB. No atomics anywhere.
__global__ __launch_bounds__(256) void k_layer1(const float* __restrict__ W1,
                                                const float* __restrict__ b1) {
    extern __shared__ float sW[];                 // FD*FD = 16384 floats
    for (int i = threadIdx.x; i < FD * FD; i += 256) sW[i] = W1[i];
    __syncthreads();
    int warp = threadIdx.x >> 5, lane = threadIdx.x & 31;
    float2 bias_lo = ((const float2*)b1)[lane];
    float2 bias_hi = ((const float2*)(b1 + 64))[lane];
    const float4* A4 = (const float4*)g_bufA;
    for (int d = blockIdx.x * 8 + warp; d < NN; d += gridDim.x * 8) {
        int beg = g_off[d], end = g_off[d + 1];
        float4 acc = make_float4(0.f, 0.f, 0.f, 0.f);
        for (int base = beg; base < end; base += 32) {
            int n = min(32, end - base);
            int sid = (base + lane < end) ? g_csr[base + lane] : 0;
            for (int t = 0; t < n; ++t) {
                int s = __shfl_sync(0xffffffffu, sid, t);
                float4 v = A4[s * 32 + lane];
                acc.x += v.x; acc.y += v.y; acc.z += v.z; acc.w += v.w;
            }
        }
        float rin = g_rsi[d];
        float4 x = make_float4(acc.x * rin, acc.y * rin, acc.z * rin, acc.w * rin);
        float a0 = 0.f, a1 = 0.f, a2 = 0.f, a3 = 0.f;
#pragma unroll
        for (int kb = 0; kb < 32; ++kb) {
            float x0 = __shfl_sync(0xffffffffu, x.x, kb);
            float x1 = __shfl_sync(0xffffffffu, x.y, kb);
            float x2 = __shfl_sync(0xffffffffu, x.z, kb);
            float x3 = __shfl_sync(0xffffffffu, x.w, kb);
            const float* wr = sW + (4 * kb) * FD;
            float2 wa, wb;
            wa = *(const float2*)(wr + 2 * lane);
            wb = *(const float2*)(wr + 64 + 2 * lane);
            a0 = fmaf(x0, wa.x, a0); a1 = fmaf(x0, wa.y, a1);
            a2 = fmaf(x0, wb.x, a2); a3 = fmaf(x0, wb.y, a3);
            wa = *(const float2*)(wr + FD + 2 * lane);
            wb = *(const float2*)(wr + FD + 64 + 2 * lane);
            a0 = fmaf(x1, wa.x, a0); a1 = fmaf(x1, wa.y, a1);
            a2 = fmaf(x1, wb.x, a2); a3 = fmaf(x1, wb.y, a3);
            wa = *(const float2*)(wr + 2 * FD + 2 * lane);
            wb = *(const float2*)(wr + 2 * FD + 64 + 2 * lane);
            a0 = fmaf(x2, wa.x, a0); a1 = fmaf(x2, wa.y, a1);
            a2 = fmaf(x2, wb.x, a2); a3 = fmaf(x2, wb.y, a3);
            wa = *(const float2*)(wr + 3 * FD + 2 * lane);
            wb = *(const float2*)(wr + 3 * FD + 64 + 2 * lane);
            a0 = fmaf(x3, wa.x, a0); a1 = fmaf(x3, wa.y, a1);
            a2 = fmaf(x3, wb.x, a2); a3 = fmaf(x3, wb.y, a3);
        }
        float rout = g_rso[d];
        float o0 = fmaxf(a0 + bias_lo.x, 0.f) * rout;
        float o1 = fmaxf(a1 + bias_lo.y, 0.f) * rout;
        float o2 = fmaxf(a2 + bias_hi.x, 0.f) * rout;
        float o3 = fmaxf(a3 + bias_hi.y, 0.f) * rout;
        float* orow = g_bufB + (long)d * FD;
        *(float2*)(orow + 2 * lane)      = make_float2(o0, o1);
        *(float2*)(orow + 64 + 2 * lane) = make_float2(o2, o3);
    }
}

// y = bufB @ W2  (50k x 40), W2 padded to 64 cols in smem. No bias/scale here.
__global__ __launch_bounds__(256) void k_gemm2y(const float* __restrict__ W2) {
    __shared__ float sW[FD * 64];
    for (int i = threadIdx.x; i < FD * 64; i += 256) {
        int k = i >> 6, c = i & 63;
        sW[i] = (c < CLS) ? W2[k * CLS + c] : 0.f;
    }
    __syncthreads();
    int warp = threadIdx.x >> 5, lane = threadIdx.x & 31;
    for (int r = blockIdx.x * 8 + warp; r < NN; r += gridDim.x * 8) {
        float4 x = ((const float4*)(g_bufB + (long)r * FD))[lane];
        float a0 = 0.f, a1 = 0.f;
#pragma unroll
        for (int kb = 0; kb < 32; ++kb) {
            float x0 = __shfl_sync(0xffffffffu, x.x, kb);
            float x1 = __shfl_sync(0xffffffffu, x.y, kb);
            float x2 = __shfl_sync(0xffffffffu, x.z, kb);
            float x3 = __shfl_sync(0xffffffffu, x.w, kb);
            const float* wp = &sW[(4 * kb) * 64];
            a0 = fmaf(x0, wp[lane],        a0); a1 = fmaf(x0, wp[32 + lane],  a1);
            a0 = fmaf(x1, wp[64 + lane],   a0); a1 = fmaf(x1, wp[96 + lane],  a1);
            a0 = fmaf(x2, wp[128 + lane],  a0); a1 = fmaf(x2, wp[160 + lane], a1);
            a0 = fmaf(x3, wp[192 + lane],  a0); a1 = fmaf(x3, wp[224 + lane], a1);
        }
        float* yrow = g_y + (long)r * CLS;
        yrow[lane] = a0;
        if (lane < 8) yrow[32 + lane] = a1;
    }
}

// Pull-based layer-2 aggregation over 40-dim rows: out = rsi*sum y[src] + b2
__global__ __launch_bounds__(256) void k_spmm2(const float* __restrict__ b2,
                                               float* __restrict__ out) {
    int warp = threadIdx.x >> 5, lane = threadIdx.x & 31;
    int d = blockIdx.x * 8 + warp;
    if (d >= NN) return;
    int beg = g_off[d], end = g_off[d + 1];
    float a0 = 0.f, a1 = 0.f;
    for (int base = beg; base < end; base += 32) {
        int n = min(32, end - base);
        int sid = (base + lane < end) ? g_csr[base + lane] : 0;
        for (int t = 0; t < n; ++t) {
            int s = __shfl_sync(0xffffffffu, sid, t);
            const float* yrow = g_y + (long)s * CLS;
            a0 += yrow[lane];
            if (lane < 8) a1 += yrow[32 + lane];
        }
    }
    float rin = g_rsi[d];
    float* orow = out + (long)d * CLS;
    orow[lane] = a0 * rin + b2[lane];
    if (lane < 8) orow[32 + lane] = a1 * rin + b2[32 + lane];
}

extern "C" void kernel_launch(void* const* d_in, const int* in_sizes, int n_in,
                              void* d_out, int out_size) {
    const int*   feat = (const int*)  d_in[0];
    const int*   src  = (const int*)  d_in[1];
    const int*   dst  = (const int*)  d_in[2];
    const float* emb  = (const float*)d_in[3];
    const float* W1   = (const float*)d_in[4];
    const float* b1   = (const float*)d_in[5];
    const float* W2   = (const float*)d_in[6];
    const float* b2   = (const float*)d_in[7];
    float* out = (float*)d_out;

    cudaFuncSetAttribute(k_layer1, cudaFuncAttributeMaxDynamicSharedMemorySize,
                         FD * FD * (int)sizeof(float));

    k_zero<<<NB, 256>>>();
    k_deg<<<(NE + 255) / 256, 256>>>(src, dst);
    k_rs<<<NB, 256>>>();
    k_scanA<<<NB, 256>>>();
    k_scanB<<<1, 256>>>();
    k_scanC<<<NB, 256>>>();
    k_fill<<<(NE + 255) / 256, 256>>>(src, dst);
    k_embed<<<NN / 8, 256>>>(feat, emb);                       // 6250 blocks
    k_layer1<<<444, 256, FD * FD * sizeof(float)>>>(W1, b1);   // 3 blocks/SM
    k_gemm2y<<<625, 256>>>(W2);
    k_spmm2<<<NN / 8, 256>>>(b2, out);
}

// round 4
// speedup vs baseline: 2.4496x; 1.1225x over previous
#include <cuda_runtime.h>
#include <cuda_fp16.h>

// GCN: embedding mean-pool -> GraphConv(128->128, relu) -> GraphConv(128->40)
// Pull-based CSR (built on the fly), no float atomics.
// fp16 staging for gather-heavy buffers; all accumulation/GEMM in fp32.
//
//   hA  = fp16( rso * meanpool(emb[features]) )                  (k_embed)
//   CSR by dst                                                   (scan + fill)
//   per dst d (fused k_layer1):
//     x  = rsi * sum_{e->d} hA[src]          (fp32 accum)
//     o  = rso * relu(x @ W1 + b1)
//     yh[d] = fp16( o @ W2 )                  [S(hW2) = (Sh)W2 reorder]
//   out = rsi * sum_{e->d} yh[src] + b2                          (k_spmm2)

#define NN  50000
#define NE  800000
#define FD  128
#define SEQ 20
#define CLS 40
#define NB  ((NN + 255) / 256)   // 196 scan blocks

static __device__ __half2 g_hA[(size_t)NN * 64];   // 128 halves/node
static __device__ __half  g_yh[(size_t)NN * CLS];
static __device__ int   g_odeg[NN];
static __device__ int   g_ideg[NN];
static __device__ float g_rso[NN];
static __device__ float g_rsi[NN];
static __device__ int   g_off[NN + 1];
static __device__ int   g_cur[NN];
static __device__ int   g_csr[NE];
static __device__ int   g_btot[256];
static __device__ int   g_bscan[256];

__global__ __launch_bounds__(256) void k_zero() {
    int i = blockIdx.x * 256 + threadIdx.x;
    if (i < NN) { g_odeg[i] = 0; g_ideg[i] = 0; g_cur[i] = 0; }
}

__global__ __launch_bounds__(256) void k_deg(const int* __restrict__ src,
                                             const int* __restrict__ dst) {
    int e = blockIdx.x * 256 + threadIdx.x;
    if (e < NE) {
        atomicAdd(&g_odeg[src[e]], 1);
        atomicAdd(&g_ideg[dst[e]], 1);
    }
}

__global__ __launch_bounds__(256) void k_rs() {
    int i = blockIdx.x * 256 + threadIdx.x;
    if (i < NN) {
        g_rso[i] = rsqrtf((float)max(g_odeg[i], 1));
        g_rsi[i] = rsqrtf((float)max(g_ideg[i], 1));
    }
}

// ---- 3-phase exclusive scan of g_ideg -> g_off ----
__global__ __launch_bounds__(256) void k_scanA() {
    __shared__ int s[256];
    int tid = threadIdx.x;
    int i = blockIdx.x * 256 + tid;
    int v = (i < NN) ? g_ideg[i] : 0;
    s[tid] = v; __syncthreads();
#pragma unroll
    for (int st = 1; st < 256; st <<= 1) {
        int t = (tid >= st) ? s[tid - st] : 0;
        __syncthreads();
        s[tid] += t;
        __syncthreads();
    }
    if (i < NN) g_off[i] = s[tid] - v;
    if (tid == 255) g_btot[blockIdx.x] = s[255];
}

__global__ __launch_bounds__(256) void k_scanB() {
    __shared__ int s[256];
    int tid = threadIdx.x;
    int v = (tid < NB) ? g_btot[tid] : 0;
    s[tid] = v; __syncthreads();
#pragma unroll
    for (int st = 1; st < 256; st <<= 1) {
        int t = (tid >= st) ? s[tid - st] : 0;
        __syncthreads();
        s[tid] += t;
        __syncthreads();
    }
    g_bscan[tid] = s[tid] - v;
}

__global__ __launch_bounds__(256) void k_scanC() {
    int i = blockIdx.x * 256 + threadIdx.x;
    if (i < NN) g_off[i] += g_bscan[i >> 8];
    if (i == 0) g_off[NN] = NE;
}

__global__ __launch_bounds__(256) void k_fill(const int* __restrict__ src,
                                              const int* __restrict__ dst) {
    int e = blockIdx.x * 256 + threadIdx.x;
    if (e < NE) {
        int d = dst[e];
        int p = g_off[d] + atomicAdd(&g_cur[d], 1);
        g_csr[p] = src[e];
    }
}

// warp per node: mean-pool 20 embedding rows, fold 1/count and rsqrt(out_deg),
// store as fp16 (8B per lane).
__global__ __launch_bounds__(256) void k_embed(const int* __restrict__ feat,
                                               const float* __restrict__ emb) {
    int w    = (blockIdx.x * 256 + threadIdx.x) >> 5;
    int lane = threadIdx.x & 31;
    if (w >= NN) return;
    int tok = 0;
    if (lane < SEQ) tok = feat[w * SEQ + lane];
    unsigned nzm = __ballot_sync(0xffffffffu, (lane < SEQ) && (tok != 0));
    float inv_cnt = 1.0f / (float)max(__popc(nzm), 1);
    float4 acc = make_float4(0.f, 0.f, 0.f, 0.f);
#pragma unroll
    for (int t = 0; t < SEQ; ++t) {
        int tk = __shfl_sync(0xffffffffu, tok, t);
        float4 v = ((const float4*)(emb + (long)tk * FD))[lane];
        acc.x += v.x; acc.y += v.y; acc.z += v.z; acc.w += v.w;
    }
    float s = g_rso[w] * inv_cnt;
    __half2 h0 = __floats2half2_rn(acc.x * s, acc.y * s);
    __half2 h1 = __floats2half2_rn(acc.z * s, acc.w * s);
    uint2 packed;
    packed.x = *(unsigned*)&h0;
    packed.y = *(unsigned*)&h1;
    ((uint2*)g_hA)[(long)w * 32 + lane] = packed;
}

// Fused layer1 + projection: warp per dst node.
//  - CSR gather fp16 rows, fp32 accumulate, scale by rsi
//  - GEMM vs W1 (64KB smem), bias+relu+rso  -> o (4 cols/lane)
//  - o @ W2 (32KB smem, padded to 64 cols)  -> yh (fp16)
__global__ __launch_bounds__(384) void k_layer1(const float* __restrict__ W1,
                                                const float* __restrict__ b1,
                                                const float* __restrict__ W2) {
    extern __shared__ float smem[];
    float* sW1 = smem;                 // FD*FD   = 16384 floats (64KB)
    float* sW2 = smem + FD * FD;       // FD*64   =  8192 floats (32KB)
    for (int i = threadIdx.x; i < FD * FD; i += 384) sW1[i] = W1[i];
    for (int i = threadIdx.x; i < FD * 64; i += 384) {
        int k = i >> 6, c = i & 63;
        sW2[i] = (c < CLS) ? W2[k * CLS + c] : 0.f;
    }
    __syncthreads();
    int warp = threadIdx.x >> 5, lane = threadIdx.x & 31;
    float2 bias_lo = ((const float2*)b1)[lane];
    float2 bias_hi = ((const float2*)(b1 + 64))[lane];
    const uint2* A2 = (const uint2*)g_hA;
    for (int d = blockIdx.x * 12 + warp; d < NN; d += gridDim.x * 12) {
        int beg = g_off[d], end = g_off[d + 1];
        float4 acc = make_float4(0.f, 0.f, 0.f, 0.f);
        for (int base = beg; base < end; base += 32) {
            int n = min(32, end - base);
            int sid = (base + lane < end) ? g_csr[base + lane] : 0;
            for (int t = 0; t < n; ++t) {
                int s = __shfl_sync(0xffffffffu, sid, t);
                uint2 raw = A2[(long)s * 32 + lane];
                __half2 h0 = *(__half2*)&raw.x;
                __half2 h1 = *(__half2*)&raw.y;
                float2 f0 = __half22float2(h0);
                float2 f1 = __half22float2(h1);
                acc.x += f0.x; acc.y += f0.y; acc.z += f1.x; acc.w += f1.y;
            }
        }
        float rin = g_rsi[d];
        float4 x = make_float4(acc.x * rin, acc.y * rin, acc.z * rin, acc.w * rin);
        float a0 = 0.f, a1 = 0.f, a2 = 0.f, a3 = 0.f;
#pragma unroll
        for (int kb = 0; kb < 32; ++kb) {
            float x0 = __shfl_sync(0xffffffffu, x.x, kb);
            float x1 = __shfl_sync(0xffffffffu, x.y, kb);
            float x2 = __shfl_sync(0xffffffffu, x.z, kb);
            float x3 = __shfl_sync(0xffffffffu, x.w, kb);
            const float* wr = sW1 + (4 * kb) * FD;
            float2 wa, wb;
            wa = *(const float2*)(wr + 2 * lane);
            wb = *(const float2*)(wr + 64 + 2 * lane);
            a0 = fmaf(x0, wa.x, a0); a1 = fmaf(x0, wa.y, a1);
            a2 = fmaf(x0, wb.x, a2); a3 = fmaf(x0, wb.y, a3);
            wa = *(const float2*)(wr + FD + 2 * lane);
            wb = *(const float2*)(wr + FD + 64 + 2 * lane);
            a0 = fmaf(x1, wa.x, a0); a1 = fmaf(x1, wa.y, a1);
            a2 = fmaf(x1, wb.x, a2); a3 = fmaf(x1, wb.y, a3);
            wa = *(const float2*)(wr + 2 * FD + 2 * lane);
            wb = *(const float2*)(wr + 2 * FD + 64 + 2 * lane);
            a0 = fmaf(x2, wa.x, a0); a1 = fmaf(x2, wa.y, a1);
            a2 = fmaf(x2, wb.x, a2); a3 = fmaf(x2, wb.y, a3);
            wa = *(const float2*)(wr + 3 * FD + 2 * lane);
            wb = *(const float2*)(wr + 3 * FD + 64 + 2 * lane);
            a0 = fmaf(x3, wa.x, a0); a1 = fmaf(x3, wa.y, a1);
            a2 = fmaf(x3, wb.x, a2); a3 = fmaf(x3, wb.y, a3);
        }
        float rout = g_rso[d];
        // lane owns layer-1 output cols {2l, 2l+1, 64+2l, 65+2l}
        float o0 = fmaxf(a0 + bias_lo.x, 0.f) * rout;
        float o1 = fmaxf(a1 + bias_lo.y, 0.f) * rout;
        float o2 = fmaxf(a2 + bias_hi.x, 0.f) * rout;
        float o3 = fmaxf(a3 + bias_hi.y, 0.f) * rout;
        // fused projection: y = o @ W2 (padded to 64 cols; lane -> {lane, 32+lane})
        float y0 = 0.f, y1 = 0.f;
#pragma unroll
        for (int kb = 0; kb < 32; ++kb) {
            float o0b = __shfl_sync(0xffffffffu, o0, kb);   // k = 2kb
            float o1b = __shfl_sync(0xffffffffu, o1, kb);   // k = 2kb+1
            float o2b = __shfl_sync(0xffffffffu, o2, kb);   // k = 64+2kb
            float o3b = __shfl_sync(0xffffffffu, o3, kb);   // k = 65+2kb
            const float* w0 = sW2 + (2 * kb) * 64;
            y0 = fmaf(o0b, w0[lane], y0);       y1 = fmaf(o0b, w0[32 + lane], y1);
            y0 = fmaf(o1b, w0[64 + lane], y0);  y1 = fmaf(o1b, w0[96 + lane], y1);
            const float* w2p = sW2 + (64 + 2 * kb) * 64;
            y0 = fmaf(o2b, w2p[lane], y0);      y1 = fmaf(o2b, w2p[32 + lane], y1);
            y0 = fmaf(o3b, w2p[64 + lane], y0); y1 = fmaf(o3b, w2p[96 + lane], y1);
        }
        __half* yr = g_yh + (long)d * CLS;
        yr[lane] = __float2half_rn(y0);
        if (lane < 8) yr[32 + lane] = __float2half_rn(y1);
    }
}

// Pull-based layer-2 aggregation over fp16 40-dim rows:
// out = rsi * sum yh[src] + b2   (fp32 accumulate)
__global__ __launch_bounds__(256) void k_spmm2(const float* __restrict__ b2,
                                               float* __restrict__ out) {
    int warp = threadIdx.x >> 5, lane = threadIdx.x & 31;
    int d = blockIdx.x * 8 + warp;
    if (d >= NN) return;
    int beg = g_off[d], end = g_off[d + 1];
    float a0 = 0.f, a1 = 0.f;
    for (int base = beg; base < end; base += 32) {
        int n = min(32, end - base);
        int sid = (base + lane < end) ? g_csr[base + lane] : 0;
        for (int t = 0; t < n; ++t) {
            int s = __shfl_sync(0xffffffffu, sid, t);
            const __half* yr = g_yh + (long)s * CLS;
            a0 += __half2float(yr[lane]);
            if (lane < 8) a1 += __half2float(yr[32 + lane]);
        }
    }
    float rin = g_rsi[d];
    float* orow = out + (long)d * CLS;
    orow[lane] = a0 * rin + b2[lane];
    if (lane < 8) orow[32 + lane] = a1 * rin + b2[32 + lane];
}

extern "C" void kernel_launch(void* const* d_in, const int* in_sizes, int n_in,
                              void* d_out, int out_size) {
    const int*   feat = (const int*)  d_in[0];
    const int*   src  = (const int*)  d_in[1];
    const int*   dst  = (const int*)  d_in[2];
    const float* emb  = (const float*)d_in[3];
    const float* W1   = (const float*)d_in[4];
    const float* b1   = (const float*)d_in[5];
    const float* W2   = (const float*)d_in[6];
    const float* b2   = (const float*)d_in[7];
    float* out = (float*)d_out;

    const int smem1 = (FD * FD + FD * 64) * (int)sizeof(float);   // 96KB
    cudaFuncSetAttribute(k_layer1, cudaFuncAttributeMaxDynamicSharedMemorySize,
                         smem1);

    k_zero<<<NB, 256>>>();
    k_deg<<<(NE + 255) / 256, 256>>>(src, dst);
    k_rs<<<NB, 256>>>();
    k_scanA<<<NB, 256>>>();
    k_scanB<<<1, 256>>>();
    k_scanC<<<NB, 256>>>();
    k_fill<<<(NE + 255) / 256, 256>>>(src, dst);
    k_embed<<<NN / 8, 256>>>(feat, emb);                 // 6250 blocks
    k_layer1<<<296, 384, smem1>>>(W1, b1, W2);           // 2 blocks/SM
    k_spmm2<<<NN / 8, 256>>>(b2, out);
}

// round 6
// speedup vs baseline: 3.4219x; 1.3969x over previous
#include <cuda_runtime.h>
#include <cuda_fp16.h>

// GCN: embedding mean-pool -> GraphConv(128->128, relu) -> GraphConv(128->40)
// Pull-based CSR, fp16-staged gathers, fused layer1+projection with
// 4-node/warp batching and packed f32x2 FMA (k-half pairing).
//
// Column-group layout for hA rows: group g (8B) = halves of cols
// (2g, 2g+1, 64+2g, 65+2g) -> lane l reads its packed x pairs directly.

#define NN   50000
#define NE   800000
#define FD   128
#define SEQ  20
#define CLS  40
#define VOC  32000
#define NB   ((NN + 255) / 256)

static __device__ __half  g_embH[(size_t)VOC * FD];     // fp16 emb table
static __device__ __half2 g_hA[(size_t)NN * 64];        // 128 halves/node
static __device__ __half  g_yh[(size_t)NN * CLS];
static __device__ int   g_odeg[NN];
static __device__ int   g_ideg[NN];
static __device__ float g_rso[NN];
static __device__ float g_rsi[NN];
static __device__ int   g_off[NN + 1];
static __device__ int   g_cur[NN];
static __device__ int   g_csr[NE];
static __device__ int   g_btot[256];
static __device__ int   g_bscan[256];

__device__ __forceinline__ unsigned long long pack2(float lo, float hi) {
    unsigned long long r;
    asm("mov.b64 %0, {%1, %2};" : "=l"(r) : "f"(lo), "f"(hi));
    return r;
}
__device__ __forceinline__ float2 unpack2(unsigned long long v) {
    float lo, hi;
    asm("mov.b64 {%0, %1}, %2;" : "=f"(lo), "=f"(hi) : "l"(v));
    return make_float2(lo, hi);
}
__device__ __forceinline__ void ffma2(unsigned long long& d,
                                      unsigned long long a,
                                      unsigned long long b) {
    asm("fma.rn.f32x2 %0, %1, %2, %0;" : "+l"(d) : "l"(a), "l"(b));
}

__global__ __launch_bounds__(256) void k_zero() {
    int i = blockIdx.x * 256 + threadIdx.x;
    if (i < NN) { g_odeg[i] = 0; g_ideg[i] = 0; g_cur[i] = 0; }
}

__global__ __launch_bounds__(256) void k_deg(const int* __restrict__ src,
                                             const int* __restrict__ dst) {
    int e = blockIdx.x * 256 + threadIdx.x;
    if (e < NE) {
        atomicAdd(&g_odeg[src[e]], 1);
        atomicAdd(&g_ideg[dst[e]], 1);
    }
}

__global__ __launch_bounds__(256) void k_rs() {
    int i = blockIdx.x * 256 + threadIdx.x;
    if (i < NN) {
        g_rso[i] = rsqrtf((float)max(g_odeg[i], 1));
        g_rsi[i] = rsqrtf((float)max(g_ideg[i], 1));
    }
}

// fp32 -> fp16 embedding table (2.048M half2 pairs)
__global__ __launch_bounds__(256) void k_conv(const float* __restrict__ emb) {
    int i = blockIdx.x * 256 + threadIdx.x;
    if (i < VOC * FD / 2) {
        float2 f = ((const float2*)emb)[i];
        ((__half2*)g_embH)[i] = __floats2half2_rn(f.x, f.y);
    }
}

// ---- 3-phase exclusive scan of g_ideg -> g_off ----
__global__ __launch_bounds__(256) void k_scanA() {
    __shared__ int s[256];
    int tid = threadIdx.x;
    int i = blockIdx.x * 256 + tid;
    int v = (i < NN) ? g_ideg[i] : 0;
    s[tid] = v; __syncthreads();
#pragma unroll
    for (int st = 1; st < 256; st <<= 1) {
        int t = (tid >= st) ? s[tid - st] : 0;
        __syncthreads();
        s[tid] += t;
        __syncthreads();
    }
    if (i < NN) g_off[i] = s[tid] - v;
    if (tid == 255) g_btot[blockIdx.x] = s[255];
}

__global__ __launch_bounds__(256) void k_scanB() {
    __shared__ int s[256];
    int tid = threadIdx.x;
    int v = (tid < NB) ? g_btot[tid] : 0;
    s[tid] = v; __syncthreads();
#pragma unroll
    for (int st = 1; st < 256; st <<= 1) {
        int t = (tid >= st) ? s[tid - st] : 0;
        __syncthreads();
        s[tid] += t;
        __syncthreads();
    }
    g_bscan[tid] = s[tid] - v;
}

__global__ __launch_bounds__(256) void k_scanC() {
    int i = blockIdx.x * 256 + threadIdx.x;
    if (i < NN) g_off[i] += g_bscan[i >> 8];
    if (i == 0) g_off[NN] = NE;
}

__global__ __launch_bounds__(256) void k_fill(const int* __restrict__ src,
                                              const int* __restrict__ dst) {
    int e = blockIdx.x * 256 + threadIdx.x;
    if (e < NE) {
        int d = dst[e];
        int p = g_off[d] + atomicAdd(&g_cur[d], 1);
        g_csr[p] = src[e];
    }
}

// warp per node: mean-pool 20 fp16 embedding rows, fold 1/count and rso,
// store in column-group layout: uint index 2g = halves(2g,2g+1),
// uint index 2g+1 = halves(64+2g, 65+2g).
__global__ __launch_bounds__(256) void k_embed(const int* __restrict__ feat) {
    int w    = (blockIdx.x * 256 + threadIdx.x) >> 5;
    int lane = threadIdx.x & 31;
    if (w >= NN) return;
    int tok = 0;
    if (lane < SEQ) tok = feat[w * SEQ + lane];
    unsigned nzm = __ballot_sync(0xffffffffu, (lane < SEQ) && (tok != 0));
    float inv_cnt = 1.0f / (float)max(__popc(nzm), 1);
    float4 acc = make_float4(0.f, 0.f, 0.f, 0.f);
#pragma unroll
    for (int t = 0; t < SEQ; ++t) {
        int tk = __shfl_sync(0xffffffffu, tok, t);
        uint2 raw = ((const uint2*)(g_embH + (long)tk * FD))[lane];  // cols 4l..4l+3
        float2 f0 = __half22float2(*(__half2*)&raw.x);
        float2 f1 = __half22float2(*(__half2*)&raw.y);
        acc.x += f0.x; acc.y += f0.y; acc.z += f1.x; acc.w += f1.y;
    }
    float s = g_rso[w] * inv_cnt;
    __half2 h01 = __floats2half2_rn(acc.x * s, acc.y * s);
    __half2 h23 = __floats2half2_rn(acc.z * s, acc.w * s);
    unsigned v01 = *(unsigned*)&h01;
    unsigned v23 = *(unsigned*)&h23;
    unsigned* rp = (unsigned*)(g_hA + (long)w * 64);
    if (lane < 16) {                    // cols 4l..4l+3 -> groups 2l,2l+1 slot01
        rp[4 * lane]     = v01;
        rp[4 * lane + 2] = v23;
    } else {                            // cols in [64,128) -> slot23
        rp[4 * lane - 63] = v01;        // group 2l-32, +4B
        rp[4 * lane - 61] = v23;        // group 2l-31, +4B
    }
}

// Fused layer1 + projection. Warp handles 4 nodes per pass:
//  - CSR gather fp16 column-group rows, fp32 accumulate
//  - GEMM vs W1 (smem, k-half interleaved u64 pairs), f32x2 FMA
//  - bias + relu + rso, fused o @ W2 (also k-half interleaved), fp16 out
__global__ __launch_bounds__(256, 2) void k_layer1(const float* __restrict__ W1,
                                                   const float* __restrict__ b1,
                                                   const float* __restrict__ W2) {
    extern __shared__ unsigned long long smemp[];
    unsigned long long* sW1p = smemp;             // 64*128 u64 = 64KB
    unsigned long long* sW2p = smemp + 64 * 128;  // 64*64  u64 = 32KB
    for (int i = threadIdx.x; i < 64 * 128; i += 256) {
        int kp = i >> 7, c = i & 127;
        sW1p[i] = pack2(W1[kp * FD + c], W1[(kp + 64) * FD + c]);
    }
    for (int i = threadIdx.x; i < 64 * 64; i += 256) {
        int kp = i >> 6, c = i & 63;
        float lo = (c < CLS) ? W2[kp * CLS + c] : 0.f;
        float hi = (c < CLS) ? W2[(kp + 64) * CLS + c] : 0.f;
        sW2p[i] = pack2(lo, hi);
    }
    __syncthreads();
    int warp = threadIdx.x >> 5, lane = threadIdx.x & 31;
    float2 blo = ((const float2*)b1)[lane];        // cols 2l, 2l+1
    float2 bhi = ((const float2*)(b1 + 64))[lane]; // cols 64+2l, 65+2l
    const uint2* A2 = (const uint2*)g_hA;
    int nwarps = gridDim.x * 8;
    for (int b = blockIdx.x * 8 + warp; b < NN / 4; b += nwarps) {
        unsigned long long px0[4], px1[4];
        float rout[4];
#pragma unroll
        for (int j = 0; j < 4; ++j) {
            int d = b * 4 + j;
            int beg = g_off[d], end = g_off[d + 1];
            float2 lo = make_float2(0.f, 0.f), hi = make_float2(0.f, 0.f);
            for (int base = beg; base < end; base += 32) {
                int n = min(32, end - base);
                int sid = (base + lane < end) ? g_csr[base + lane] : 0;
                for (int t = 0; t < n; ++t) {
                    int s = __shfl_sync(0xffffffffu, sid, t);
                    uint2 raw = A2[(long)s * 32 + lane];
                    float2 f0 = __half22float2(*(__half2*)&raw.x);
                    float2 f1 = __half22float2(*(__half2*)&raw.y);
                    lo.x += f0.x; lo.y += f0.y; hi.x += f1.x; hi.y += f1.y;
                }
            }
            float rin = g_rsi[d];
            px0[j] = pack2(lo.x * rin, hi.x * rin);   // (x_{2l},   x_{64+2l})
            px1[j] = pack2(lo.y * rin, hi.y * rin);   // (x_{2l+1}, x_{65+2l})
            rout[j] = g_rso[d];
        }
        // GEMM: acc[j][c'] packed (even-k-half sum, odd-k-half sum) for
        // output cols c' in {2l, 2l+1, 64+2l, 65+2l}
        unsigned long long acc[4][4];
#pragma unroll
        for (int j = 0; j < 4; ++j)
#pragma unroll
            for (int c = 0; c < 4; ++c) acc[j][c] = 0ull;
#pragma unroll 2
        for (int g = 0; g < 32; ++g) {
            const ulonglong2* w0 = (const ulonglong2*)&sW1p[(2 * g) * FD];
            const ulonglong2* w1 = (const ulonglong2*)&sW1p[(2 * g + 1) * FD];
            ulonglong2 wlo0 = w0[lane], whi0 = w0[32 + lane];
            ulonglong2 wlo1 = w1[lane], whi1 = w1[32 + lane];
#pragma unroll
            for (int j = 0; j < 4; ++j) {
                unsigned long long b0 = __shfl_sync(0xffffffffu, px0[j], g);
                ffma2(acc[j][0], b0, wlo0.x); ffma2(acc[j][1], b0, wlo0.y);
                ffma2(acc[j][2], b0, whi0.x); ffma2(acc[j][3], b0, whi0.y);
                unsigned long long b1v = __shfl_sync(0xffffffffu, px1[j], g);
                ffma2(acc[j][0], b1v, wlo1.x); ffma2(acc[j][1], b1v, wlo1.y);
                ffma2(acc[j][2], b1v, whi1.x); ffma2(acc[j][3], b1v, whi1.y);
            }
        }
        // epilogue + repack for projection
        unsigned long long pp0[4], pp1[4];
#pragma unroll
        for (int j = 0; j < 4; ++j) {
            float2 u0 = unpack2(acc[j][0]), u1 = unpack2(acc[j][1]);
            float2 u2 = unpack2(acc[j][2]), u3 = unpack2(acc[j][3]);
            float o0 = fmaxf(u0.x + u0.y + blo.x, 0.f) * rout[j];  // col 2l
            float o1 = fmaxf(u1.x + u1.y + blo.y, 0.f) * rout[j];  // col 2l+1
            float o2 = fmaxf(u2.x + u2.y + bhi.x, 0.f) * rout[j];  // col 64+2l
            float o3 = fmaxf(u3.x + u3.y + bhi.y, 0.f) * rout[j];  // col 65+2l
            pp0[j] = pack2(o0, o2);
            pp1[j] = pack2(o1, o3);
        }
        // projection: ay[j][0] -> out col lane, ay[j][1] -> col 32+lane
        unsigned long long ay[4][2];
#pragma unroll
        for (int j = 0; j < 4; ++j) { ay[j][0] = 0ull; ay[j][1] = 0ull; }
#pragma unroll 2
        for (int g = 0; g < 32; ++g) {
            unsigned long long wa0 = sW2p[(2 * g) * 64 + lane];
            unsigned long long wb0 = sW2p[(2 * g) * 64 + 32 + lane];
            unsigned long long wa1 = sW2p[(2 * g + 1) * 64 + lane];
            unsigned long long wb1 = sW2p[(2 * g + 1) * 64 + 32 + lane];
#pragma unroll
            for (int j = 0; j < 4; ++j) {
                unsigned long long c0 = __shfl_sync(0xffffffffu, pp0[j], g);
                ffma2(ay[j][0], c0, wa0); ffma2(ay[j][1], c0, wb0);
                unsigned long long c1 = __shfl_sync(0xffffffffu, pp1[j], g);
                ffma2(ay[j][0], c1, wa1); ffma2(ay[j][1], c1, wb1);
            }
        }
#pragma unroll
        for (int j = 0; j < 4; ++j) {
            int d = b * 4 + j;
            float2 v0 = unpack2(ay[j][0]);
            float2 v1 = unpack2(ay[j][1]);
            __half* yr = g_yh + (long)d * CLS;
            yr[lane] = __float2half_rn(v0.x + v0.y);
            if (lane < 8) yr[32 + lane] = __float2half_rn(v1.x + v1.y);
        }
    }
}

// Pull-based layer-2 aggregation: out = rsi * sum yh[src] + b2 (fp32 accum)
__global__ __launch_bounds__(256) void k_spmm2(const float* __restrict__ b2,
                                               float* __restrict__ out) {
    int warp = threadIdx.x >> 5, lane = threadIdx.x & 31;
    int d = blockIdx.x * 8 + warp;
    if (d >= NN) return;
    int beg = g_off[d], end = g_off[d + 1];
    float a0 = 0.f, a1 = 0.f;
    for (int base = beg; base < end; base += 32) {
        int n = min(32, end - base);
        int sid = (base + lane < end) ? g_csr[base + lane] : 0;
        for (int t = 0; t < n; ++t) {
            int s = __shfl_sync(0xffffffffu, sid, t);
            const __half* yr = g_yh + (long)s * CLS;
            a0 += __half2float(yr[lane]);
            if (lane < 8) a1 += __half2float(yr[32 + lane]);
        }
    }
    float rin = g_rsi[d];
    float* orow = out + (long)d * CLS;
    orow[lane] = a0 * rin + b2[lane];
    if (lane < 8) orow[32 + lane] = a1 * rin + b2[32 + lane];
}

extern "C" void kernel_launch(void* const* d_in, const int* in_sizes, int n_in,
                              void* d_out, int out_size) {
    const int*   feat = (const int*)  d_in[0];
    const int*   src  = (const int*)  d_in[1];
    const int*   dst  = (const int*)  d_in[2];
    const float* emb  = (const float*)d_in[3];
    const float* W1   = (const float*)d_in[4];
    const float* b1   = (const float*)d_in[5];
    const float* W2   = (const float*)d_in[6];
    const float* b2   = (const float*)d_in[7];
    float* out = (float*)d_out;

    const int smem1 = (64 * 128 + 64 * 64) * 8;   // 96KB
    cudaFuncSetAttribute(k_layer1, cudaFuncAttributeMaxDynamicSharedMemorySize,
                         smem1);

    k_conv<<<(VOC * FD / 2 + 255) / 256, 256>>>(emb);   // 8000 blocks
    k_zero<<<NB, 256>>>();
    k_deg<<<(NE + 255) / 256, 256>>>(src, dst);
    k_rs<<<NB, 256>>>();
    k_scanA<<<NB, 256>>>();
    k_scanB<<<1, 256>>>();
    k_scanC<<<NB, 256>>>();
    k_fill<<<(NE + 255) / 256, 256>>>(src, dst);
    k_embed<<<NN / 8, 256>>>(feat);                      // 6250 blocks
    k_layer1<<<296, 256, smem1>>>(W1, b1, W2);           // 2 blocks/SM
    k_spmm2<<<NN / 8, 256>>>(b2, out);
}

// round 7
// speedup vs baseline: 4.0476x; 1.1828x over previous
#include <cuda_runtime.h>
#include <cuda_fp16.h>

// GCN: embedding mean-pool -> GraphConv(128->128, relu) -> GraphConv(128->40)
// Linearity reorder: meanpool(emb)@W1 == meanpool(emb@W1), so precompute
// embT = emb@W1 (32000x128, fp16, column-group layout) once; layer1 becomes
// gather + bias/relu + W2 projection (no per-node 128x128 GEMM).
//
// Column-group layout (CG): row = 32 uint2 groups; group l (8B) holds fp16 of
// cols (2l, 2l+1, 64+2l, 65+2l). Elementwise ops (pooling, aggregation) are
// layout-agnostic; the k-half pairing feeds f32x2 FMA directly.

#define NN   50000
#define NE   800000
#define FD   128
#define SEQ  20
#define CLS  40
#define VOC  32000
#define NB   ((NN + 255) / 256)

static __device__ uint2 g_embT[(size_t)VOC * 32];   // emb@W1, fp16 CG layout
static __device__ uint2 g_hA[(size_t)NN * 32];      // pooled feats, fp16 CG
static __device__ __half g_yh[(size_t)NN * CLS];
static __device__ int   g_odeg[NN];
static __device__ int   g_ideg[NN];
static __device__ float g_rso[NN];
static __device__ float g_rsi[NN];
static __device__ int   g_off[NN + 1];
static __device__ int   g_cur[NN];
static __device__ int   g_csr[NE];
static __device__ int   g_btot[256];
static __device__ int   g_bscan[256];

__device__ __forceinline__ unsigned long long pack2(float lo, float hi) {
    unsigned long long r;
    asm("mov.b64 %0, {%1, %2};" : "=l"(r) : "f"(lo), "f"(hi));
    return r;
}
__device__ __forceinline__ float2 unpack2(unsigned long long v) {
    float lo, hi;
    asm("mov.b64 {%0, %1}, %2;" : "=f"(lo), "=f"(hi) : "l"(v));
    return make_float2(lo, hi);
}
__device__ __forceinline__ void ffma2(unsigned long long& d,
                                      unsigned long long a,
                                      unsigned long long b) {
    asm("fma.rn.f32x2 %0, %1, %2, %0;" : "+l"(d) : "l"(a), "l"(b));
}

// embT = emb @ W1 -> fp16 CG layout. Also zeroes deg/cur arrays (absorbs
// the old k_zero launch; visible to subsequent kernels at kernel end).
// Warp handles 4 vocab rows per pass; W1 in smem as k-half u64 pairs.
__global__ __launch_bounds__(256, 2) void k_table(const float* __restrict__ emb,
                                                  const float* __restrict__ W1) {
    // absorbed zeroing
    int gid = blockIdx.x * 256 + threadIdx.x;
    if (gid < NN) { g_odeg[gid] = 0; g_ideg[gid] = 0; g_cur[gid] = 0; }

    extern __shared__ unsigned long long sW1p[];      // 64*128 u64 = 64KB
    for (int i = threadIdx.x; i < 64 * 128; i += 256) {
        int kp = i >> 7, c = i & 127;
        sW1p[i] = pack2(W1[kp * FD + c], W1[(kp + 64) * FD + c]);
    }
    __syncthreads();
    int warp = threadIdx.x >> 5, lane = threadIdx.x & 31;
    int nwarps = gridDim.x * 8;
    for (int b = blockIdx.x * 8 + warp; b < VOC / 4; b += nwarps) {
        unsigned long long px0[4], px1[4];
#pragma unroll
        for (int j = 0; j < 4; ++j) {
            int v = b * 4 + j;
            const float* row = emb + (long)v * FD;
            float2 a = *(const float2*)(row + 2 * lane);        // x_2l, x_2l+1
            float2 c = *(const float2*)(row + 64 + 2 * lane);   // x_64+2l, x_65+2l
            px0[j] = pack2(a.x, c.x);
            px1[j] = pack2(a.y, c.y);
        }
        unsigned long long acc[4][4];
#pragma unroll
        for (int j = 0; j < 4; ++j)
#pragma unroll
            for (int c = 0; c < 4; ++c) acc[j][c] = 0ull;
#pragma unroll 2
        for (int g = 0; g < 32; ++g) {
            const ulonglong2* w0 = (const ulonglong2*)&sW1p[(2 * g) * FD];
            const ulonglong2* w1 = (const ulonglong2*)&sW1p[(2 * g + 1) * FD];
            ulonglong2 wlo0 = w0[lane], whi0 = w0[32 + lane];
            ulonglong2 wlo1 = w1[lane], whi1 = w1[32 + lane];
#pragma unroll
            for (int j = 0; j < 4; ++j) {
                unsigned long long b0 = __shfl_sync(0xffffffffu, px0[j], g);
                ffma2(acc[j][0], b0, wlo0.x); ffma2(acc[j][1], b0, wlo0.y);
                ffma2(acc[j][2], b0, whi0.x); ffma2(acc[j][3], b0, whi0.y);
                unsigned long long b1v = __shfl_sync(0xffffffffu, px1[j], g);
                ffma2(acc[j][0], b1v, wlo1.x); ffma2(acc[j][1], b1v, wlo1.y);
                ffma2(acc[j][2], b1v, whi1.x); ffma2(acc[j][3], b1v, whi1.y);
            }
        }
#pragma unroll
        for (int j = 0; j < 4; ++j) {
            int v = b * 4 + j;
            float2 u0 = unpack2(acc[j][0]), u1 = unpack2(acc[j][1]);
            float2 u2 = unpack2(acc[j][2]), u3 = unpack2(acc[j][3]);
            __half2 h01 = __floats2half2_rn(u0.x + u0.y, u1.x + u1.y); // cols 2l,2l+1
            __half2 h23 = __floats2half2_rn(u2.x + u2.y, u3.x + u3.y); // cols 64+2l,65+2l
            uint2 o;
            o.x = *(unsigned*)&h01;
            o.y = *(unsigned*)&h23;
            g_embT[(long)v * 32 + lane] = o;
        }
    }
}

__global__ __launch_bounds__(256) void k_deg(const int* __restrict__ src,
                                             const int* __restrict__ dst) {
    int e = blockIdx.x * 256 + threadIdx.x;
    if (e < NE) {
        atomicAdd(&g_odeg[src[e]], 1);
        atomicAdd(&g_ideg[dst[e]], 1);
    }
}

// ---- 3-phase exclusive scan of g_ideg -> g_off (rs folded into phase C) ----
__global__ __launch_bounds__(256) void k_scanA() {
    __shared__ int s[256];
    int tid = threadIdx.x;
    int i = blockIdx.x * 256 + tid;
    int v = (i < NN) ? g_ideg[i] : 0;
    s[tid] = v; __syncthreads();
#pragma unroll
    for (int st = 1; st < 256; st <<= 1) {
        int t = (tid >= st) ? s[tid - st] : 0;
        __syncthreads();
        s[tid] += t;
        __syncthreads();
    }
    if (i < NN) g_off[i] = s[tid] - v;
    if (tid == 255) g_btot[blockIdx.x] = s[255];
}

__global__ __launch_bounds__(256) void k_scanB() {
    __shared__ int s[256];
    int tid = threadIdx.x;
    int v = (tid < NB) ? g_btot[tid] : 0;
    s[tid] = v; __syncthreads();
#pragma unroll
    for (int st = 1; st < 256; st <<= 1) {
        int t = (tid >= st) ? s[tid - st] : 0;
        __syncthreads();
        s[tid] += t;
        __syncthreads();
    }
    g_bscan[tid] = s[tid] - v;
}

__global__ __launch_bounds__(256) void k_scanC() {
    int i = blockIdx.x * 256 + threadIdx.x;
    if (i < NN) {
        g_off[i] += g_bscan[i >> 8];
        g_rso[i] = rsqrtf((float)max(g_odeg[i], 1));
        g_rsi[i] = rsqrtf((float)max(g_ideg[i], 1));
    }
    if (i == 0) g_off[NN] = NE;
}

__global__ __launch_bounds__(256) void k_fill(const int* __restrict__ src,
                                              const int* __restrict__ dst) {
    int e = blockIdx.x * 256 + threadIdx.x;
    if (e < NE) {
        int d = dst[e];
        int p = g_off[d] + atomicAdd(&g_cur[d], 1);
        g_csr[p] = src[e];
    }
}

// warp per node: mean-pool 20 embT rows (CG layout is elementwise-safe),
// fold 1/count and rso. Coalesced uint2 load/store, no permutation.
__global__ __launch_bounds__(256) void k_embed(const int* __restrict__ feat) {
    int w    = (blockIdx.x * 256 + threadIdx.x) >> 5;
    int lane = threadIdx.x & 31;
    if (w >= NN) return;
    int tok = 0;
    if (lane < SEQ) tok = feat[w * SEQ + lane];
    unsigned nzm = __ballot_sync(0xffffffffu, (lane < SEQ) && (tok != 0));
    float inv_cnt = 1.0f / (float)max(__popc(nzm), 1);
    float4 acc = make_float4(0.f, 0.f, 0.f, 0.f);
#pragma unroll
    for (int t = 0; t < SEQ; ++t) {
        int tk = __shfl_sync(0xffffffffu, tok, t);
        uint2 raw = g_embT[(long)tk * 32 + lane];
        float2 f0 = __half22float2(*(__half2*)&raw.x);
        float2 f1 = __half22float2(*(__half2*)&raw.y);
        acc.x += f0.x; acc.y += f0.y; acc.z += f1.x; acc.w += f1.y;
    }
    float s = g_rso[w] * inv_cnt;
    __half2 h01 = __floats2half2_rn(acc.x * s, acc.y * s);
    __half2 h23 = __floats2half2_rn(acc.z * s, acc.w * s);
    uint2 o;
    o.x = *(unsigned*)&h01;
    o.y = *(unsigned*)&h23;
    g_hA[(long)w * 32 + lane] = o;
}

// Layer1 (post-reorder): warp handles 4 dst nodes.
//  - CSR gather CG rows, fp32 accumulate (this IS x@W1 already)
//  - rin scale + bias + relu + rout
//  - o @ W2 (32KB static smem, k-half interleaved), fp16 out
__global__ __launch_bounds__(256, 4) void k_layer1(const float* __restrict__ b1,
                                                   const float* __restrict__ W2) {
    __shared__ unsigned long long sW2p[64 * 64];      // 32KB
    for (int i = threadIdx.x; i < 64 * 64; i += 256) {
        int kp = i >> 6, c = i & 63;
        float lo = (c < CLS) ? W2[kp * CLS + c] : 0.f;
        float hi = (c < CLS) ? W2[(kp + 64) * CLS + c] : 0.f;
        sW2p[i] = pack2(lo, hi);
    }
    __syncthreads();
    int warp = threadIdx.x >> 5, lane = threadIdx.x & 31;
    float2 blo = ((const float2*)b1)[lane];        // cols 2l, 2l+1
    float2 bhi = ((const float2*)(b1 + 64))[lane]; // cols 64+2l, 65+2l
    int nwarps = gridDim.x * 8;
    for (int b = blockIdx.x * 8 + warp; b < NN / 4; b += nwarps) {
        unsigned long long pp0[4], pp1[4];
#pragma unroll
        for (int j = 0; j < 4; ++j) {
            int d = b * 4 + j;
            int beg = g_off[d], end = g_off[d + 1];
            float2 lo = make_float2(0.f, 0.f), hi = make_float2(0.f, 0.f);
            for (int base = beg; base < end; base += 32) {
                int n = min(32, end - base);
                int sid = (base + lane < end) ? g_csr[base + lane] : 0;
                for (int t = 0; t < n; ++t) {
                    int s = __shfl_sync(0xffffffffu, sid, t);
                    uint2 raw = g_hA[(long)s * 32 + lane];
                    float2 f0 = __half22float2(*(__half2*)&raw.x);
                    float2 f1 = __half22float2(*(__half2*)&raw.y);
                    lo.x += f0.x; lo.y += f0.y; hi.x += f1.x; hi.y += f1.y;
                }
            }
            float rin = g_rsi[d];
            float ro  = g_rso[d];
            float o0 = fmaxf(lo.x * rin + blo.x, 0.f) * ro;  // col 2l
            float o1 = fmaxf(lo.y * rin + blo.y, 0.f) * ro;  // col 2l+1
            float o2 = fmaxf(hi.x * rin + bhi.x, 0.f) * ro;  // col 64+2l
            float o3 = fmaxf(hi.y * rin + bhi.y, 0.f) * ro;  // col 65+2l
            pp0[j] = pack2(o0, o2);
            pp1[j] = pack2(o1, o3);
        }
        // projection: ay[j][0] -> out col lane, ay[j][1] -> col 32+lane
        unsigned long long ay[4][2];
#pragma unroll
        for (int j = 0; j < 4; ++j) { ay[j][0] = 0ull; ay[j][1] = 0ull; }
#pragma unroll 2
        for (int g = 0; g < 32; ++g) {
            unsigned long long wa0 = sW2p[(2 * g) * 64 + lane];
            unsigned long long wb0 = sW2p[(2 * g) * 64 + 32 + lane];
            unsigned long long wa1 = sW2p[(2 * g + 1) * 64 + lane];
            unsigned long long wb1 = sW2p[(2 * g + 1) * 64 + 32 + lane];
#pragma unroll
            for (int j = 0; j < 4; ++j) {
                unsigned long long c0 = __shfl_sync(0xffffffffu, pp0[j], g);
                ffma2(ay[j][0], c0, wa0); ffma2(ay[j][1], c0, wb0);
                unsigned long long c1 = __shfl_sync(0xffffffffu, pp1[j], g);
                ffma2(ay[j][0], c1, wa1); ffma2(ay[j][1], c1, wb1);
            }
        }
#pragma unroll
        for (int j = 0; j < 4; ++j) {
            int d = b * 4 + j;
            float2 v0 = unpack2(ay[j][0]);
            float2 v1 = unpack2(ay[j][1]);
            __half* yr = g_yh + (long)d * CLS;
            yr[lane] = __float2half_rn(v0.x + v0.y);
            if (lane < 8) yr[32 + lane] = __float2half_rn(v1.x + v1.y);
        }
    }
}

// Pull-based layer-2 aggregation: out = rsi * sum yh[src] + b2 (fp32 accum)
__global__ __launch_bounds__(256) void k_spmm2(const float* __restrict__ b2,
                                               float* __restrict__ out) {
    int warp = threadIdx.x >> 5, lane = threadIdx.x & 31;
    int d = blockIdx.x * 8 + warp;
    if (d >= NN) return;
    int beg = g_off[d], end = g_off[d + 1];
    float a0 = 0.f, a1 = 0.f;
    for (int base = beg; base < end; base += 32) {
        int n = min(32, end - base);
        int sid = (base + lane < end) ? g_csr[base + lane] : 0;
        for (int t = 0; t < n; ++t) {
            int s = __shfl_sync(0xffffffffu, sid, t);
            const __half* yr = g_yh + (long)s * CLS;
            a0 += __half2float(yr[lane]);
            if (lane < 8) a1 += __half2float(yr[32 + lane]);
        }
    }
    float rin = g_rsi[d];
    float* orow = out + (long)d * CLS;
    orow[lane] = a0 * rin + b2[lane];
    if (lane < 8) orow[32 + lane] = a1 * rin + b2[32 + lane];
}

extern "C" void kernel_launch(void* const* d_in, const int* in_sizes, int n_in,
                              void* d_out, int out_size) {
    const int*   feat = (const int*)  d_in[0];
    const int*   src  = (const int*)  d_in[1];
    const int*   dst  = (const int*)  d_in[2];
    const float* emb  = (const float*)d_in[3];
    const float* W1   = (const float*)d_in[4];
    const float* b1   = (const float*)d_in[5];
    const float* W2   = (const float*)d_in[6];
    const float* b2   = (const float*)d_in[7];
    float* out = (float*)d_out;

    const int smemT = 64 * 128 * 8;   // 64KB
    cudaFuncSetAttribute(k_table, cudaFuncAttributeMaxDynamicSharedMemorySize,
                         smemT);

    k_table<<<296, 256, smemT>>>(emb, W1);   // emb@W1 + zero deg/cur
    k_deg<<<(NE + 255) / 256, 256>>>(src, dst);
    k_scanA<<<NB, 256>>>();
    k_scanB<<<1, 256>>>();
    k_scanC<<<NB, 256>>>();                  // + rso/rsi
    k_fill<<<(NE + 255) / 256, 256>>>(src, dst);
    k_embed<<<NN / 8, 256>>>(feat);          // 6250 blocks
    k_layer1<<<592, 256>>>(b1, W2);          // 4 blocks/SM, 32KB static smem
    k_spmm2<<<NN / 8, 256>>>(b2, out);
}

// round 8
// speedup vs baseline: 4.3094x; 1.0647x over previous
#include <cuda_runtime.h>
#include <cuda_fp16.h>

// GCN: embedding mean-pool -> GraphConv(128->128, relu) -> GraphConv(128->40)
// embT = emb@W1 reorder; pull-based CSR (uint16); fp16 CG staging.
// 6 launches; independent phases merged into shared grids for overlap:
//   k_zero      : zero deg/cur/arrive
//   k_tabledeg  : [blocks<296] embT = emb@W1 (fp16 CG)  ||  [rest] degree atomics
//   k_scan      : single-launch exclusive scan (spin barrier) + rso/rsi
//   k_fillembed : [blocks<6250] mean-pool embT -> hA    ||  [rest] CSR fill
//   k_layer1    : gather hA + bias/relu + @W2 -> yh (fp16)
//   k_spmm2     : gather yh + rsi + b2 -> out

#define NN   50000
#define NE   800000
#define FD   128
#define SEQ  20
#define CLS  40
#define VOC  32000
#define NB   ((NN + 255) / 256)      // 196
#define GEMMB 296
#define DEGB  ((NE + 255) / 256)     // 3125
#define EMBB  (NN / 8)               // 6250

static __device__ uint2 g_embT[(size_t)VOC * 32];   // emb@W1, fp16 CG layout
static __device__ uint2 g_hA[(size_t)NN * 32];      // pooled feats, fp16 CG
static __device__ __half g_yh[(size_t)NN * CLS];
static __device__ int   g_odeg[NN];
static __device__ int   g_ideg[NN];
static __device__ float g_rso[NN];
static __device__ float g_rsi[NN];
static __device__ int   g_off[NN + 1];
static __device__ int   g_cur[NN];
static __device__ unsigned short g_csr[NE];
static __device__ int   g_btot[256];
static __device__ int   g_arrive;

__device__ __forceinline__ unsigned long long pack2(float lo, float hi) {
    unsigned long long r;
    asm("mov.b64 %0, {%1, %2};" : "=l"(r) : "f"(lo), "f"(hi));
    return r;
}
__device__ __forceinline__ float2 unpack2(unsigned long long v) {
    float lo, hi;
    asm("mov.b64 {%0, %1}, %2;" : "=f"(lo), "=f"(hi) : "l"(v));
    return make_float2(lo, hi);
}
__device__ __forceinline__ void ffma2(unsigned long long& d,
                                      unsigned long long a,
                                      unsigned long long b) {
    asm("fma.rn.f32x2 %0, %1, %2, %0;" : "+l"(d) : "l"(a), "l"(b));
}

__global__ __launch_bounds__(256) void k_zero() {
    int i = blockIdx.x * 256 + threadIdx.x;
    if (i < NN) { g_odeg[i] = 0; g_ideg[i] = 0; g_cur[i] = 0; }
    if (i == 0) g_arrive = 0;
}

// blocks [0,GEMMB): embT = emb @ W1 -> fp16 CG (W1 k-half pairs in smem)
// blocks [GEMMB, GEMMB+DEGB): degree atomics (one pass over edges)
__global__ __launch_bounds__(256) void k_tabledeg(const float* __restrict__ emb,
                                                  const float* __restrict__ W1,
                                                  const int* __restrict__ src,
                                                  const int* __restrict__ dst) {
    if (blockIdx.x >= GEMMB) {
        int e = (blockIdx.x - GEMMB) * 256 + threadIdx.x;
        if (e < NE) {
            atomicAdd(&g_odeg[src[e]], 1);
            atomicAdd(&g_ideg[dst[e]], 1);
        }
        return;
    }
    extern __shared__ unsigned long long sW1p[];      // 64*128 u64 = 64KB
    for (int i = threadIdx.x; i < 64 * 128; i += 256) {
        int kp = i >> 7, c = i & 127;
        sW1p[i] = pack2(W1[kp * FD + c], W1[(kp + 64) * FD + c]);
    }
    __syncthreads();
    int warp = threadIdx.x >> 5, lane = threadIdx.x & 31;
    const int nwarps = GEMMB * 8;
    for (int b = blockIdx.x * 8 + warp; b < VOC / 4; b += nwarps) {
        unsigned long long px0[4], px1[4];
#pragma unroll
        for (int j = 0; j < 4; ++j) {
            int v = b * 4 + j;
            const float* row = emb + (long)v * FD;
            float2 a = *(const float2*)(row + 2 * lane);
            float2 c = *(const float2*)(row + 64 + 2 * lane);
            px0[j] = pack2(a.x, c.x);
            px1[j] = pack2(a.y, c.y);
        }
        unsigned long long acc[4][4];
#pragma unroll
        for (int j = 0; j < 4; ++j)
#pragma unroll
            for (int c = 0; c < 4; ++c) acc[j][c] = 0ull;
#pragma unroll 2
        for (int g = 0; g < 32; ++g) {
            const ulonglong2* w0 = (const ulonglong2*)&sW1p[(2 * g) * FD];
            const ulonglong2* w1 = (const ulonglong2*)&sW1p[(2 * g + 1) * FD];
            ulonglong2 wlo0 = w0[lane], whi0 = w0[32 + lane];
            ulonglong2 wlo1 = w1[lane], whi1 = w1[32 + lane];
#pragma unroll
            for (int j = 0; j < 4; ++j) {
                unsigned long long b0 = __shfl_sync(0xffffffffu, px0[j], g);
                ffma2(acc[j][0], b0, wlo0.x); ffma2(acc[j][1], b0, wlo0.y);
                ffma2(acc[j][2], b0, whi0.x); ffma2(acc[j][3], b0, whi0.y);
                unsigned long long b1v = __shfl_sync(0xffffffffu, px1[j], g);
                ffma2(acc[j][0], b1v, wlo1.x); ffma2(acc[j][1], b1v, wlo1.y);
                ffma2(acc[j][2], b1v, whi1.x); ffma2(acc[j][3], b1v, whi1.y);
            }
        }
#pragma unroll
        for (int j = 0; j < 4; ++j) {
            int v = b * 4 + j;
            float2 u0 = unpack2(acc[j][0]), u1 = unpack2(acc[j][1]);
            float2 u2 = unpack2(acc[j][2]), u3 = unpack2(acc[j][3]);
            __half2 h01 = __floats2half2_rn(u0.x + u0.y, u1.x + u1.y);
            __half2 h23 = __floats2half2_rn(u2.x + u2.y, u3.x + u3.y);
            uint2 o;
            o.x = *(unsigned*)&h01;
            o.y = *(unsigned*)&h23;
            g_embT[(long)v * 32 + lane] = o;
        }
    }
}

// Single-launch exclusive scan of g_ideg -> g_off, plus rso/rsi.
// All NB=196 blocks are co-resident (196 < 148*8), so a device-wide
// spin barrier on g_arrive is safe.
__global__ __launch_bounds__(256) void k_scan() {
    __shared__ int s[256];
    int tid = threadIdx.x;
    int i = blockIdx.x * 256 + tid;
    int v = (i < NN) ? g_ideg[i] : 0;
    s[tid] = v; __syncthreads();
#pragma unroll
    for (int st = 1; st < 256; st <<= 1) {
        int t = (tid >= st) ? s[tid - st] : 0;
        __syncthreads();
        s[tid] += t;
        __syncthreads();
    }
    int local_ex = s[tid] - v;
    if (tid == 255) g_btot[blockIdx.x] = s[255];
    __syncthreads();
    // device-wide barrier
    if (tid == 0) {
        __threadfence();
        atomicAdd(&g_arrive, 1);
        while (atomicAdd(&g_arrive, 0) < (int)gridDim.x) {}
        __threadfence();
    }
    __syncthreads();
    // block prefix = sum of btot[0..bid)
    int pv = (tid < (int)blockIdx.x) ? g_btot[tid] : 0;
    s[tid] = pv; __syncthreads();
#pragma unroll
    for (int st = 128; st > 0; st >>= 1) {
        if (tid < st) s[tid] += s[tid + st];
        __syncthreads();
    }
    int prefix = s[0];
    if (i < NN) {
        g_off[i] = local_ex + prefix;
        g_rso[i] = rsqrtf((float)max(g_odeg[i], 1));
        g_rsi[i] = rsqrtf((float)max(g_ideg[i], 1));
    }
    if (i == 0) g_off[NN] = NE;
}

// blocks [0,EMBB): warp per node, mean-pool embT rows (CG), fold 1/cnt * rso
// blocks [EMBB, EMBB+DEGB): CSR fill (uint16 src ids)
__global__ __launch_bounds__(256) void k_fillembed(const int* __restrict__ feat,
                                                   const int* __restrict__ src,
                                                   const int* __restrict__ dst) {
    if (blockIdx.x >= EMBB) {
        int e = (blockIdx.x - EMBB) * 256 + threadIdx.x;
        if (e < NE) {
            int d = dst[e];
            int p = g_off[d] + atomicAdd(&g_cur[d], 1);
            g_csr[p] = (unsigned short)src[e];
        }
        return;
    }
    int w    = (blockIdx.x * 256 + threadIdx.x) >> 5;
    int lane = threadIdx.x & 31;
    int tok = 0;
    if (lane < SEQ) tok = feat[w * SEQ + lane];
    unsigned nzm = __ballot_sync(0xffffffffu, (lane < SEQ) && (tok != 0));
    float inv_cnt = 1.0f / (float)max(__popc(nzm), 1);
    float4 acc = make_float4(0.f, 0.f, 0.f, 0.f);
#pragma unroll
    for (int t = 0; t < SEQ; ++t) {
        int tk = __shfl_sync(0xffffffffu, tok, t);
        uint2 raw = g_embT[(long)tk * 32 + lane];
        float2 f0 = __half22float2(*(__half2*)&raw.x);
        float2 f1 = __half22float2(*(__half2*)&raw.y);
        acc.x += f0.x; acc.y += f0.y; acc.z += f1.x; acc.w += f1.y;
    }
    float sc = g_rso[w] * inv_cnt;
    __half2 h01 = __floats2half2_rn(acc.x * sc, acc.y * sc);
    __half2 h23 = __floats2half2_rn(acc.z * sc, acc.w * sc);
    uint2 o;
    o.x = *(unsigned*)&h01;
    o.y = *(unsigned*)&h23;
    g_hA[(long)w * 32 + lane] = o;
}

// Layer1: warp handles 4 dst nodes.
//  - CSR gather CG rows (this IS x@W1 already), fp32 accumulate
//  - rin + bias + relu + rout ; o @ W2 (32KB static smem) -> fp16 yh
__global__ __launch_bounds__(256, 4) void k_layer1(const float* __restrict__ b1,
                                                   const float* __restrict__ W2) {
    __shared__ unsigned long long sW2p[64 * 64];      // 32KB
    for (int i = threadIdx.x; i < 64 * 64; i += 256) {
        int kp = i >> 6, c = i & 63;
        float lo = (c < CLS) ? W2[kp * CLS + c] : 0.f;
        float hi = (c < CLS) ? W2[(kp + 64) * CLS + c] : 0.f;
        sW2p[i] = pack2(lo, hi);
    }
    __syncthreads();
    int warp = threadIdx.x >> 5, lane = threadIdx.x & 31;
    float2 blo = ((const float2*)b1)[lane];
    float2 bhi = ((const float2*)(b1 + 64))[lane];
    int nwarps = gridDim.x * 8;
    for (int b = blockIdx.x * 8 + warp; b < NN / 4; b += nwarps) {
        unsigned long long pp0[4], pp1[4];
#pragma unroll
        for (int j = 0; j < 4; ++j) {
            int d = b * 4 + j;
            int beg = g_off[d], end = g_off[d + 1];
            float2 lo = make_float2(0.f, 0.f), hi = make_float2(0.f, 0.f);
            for (int base = beg; base < end; base += 32) {
                int n = min(32, end - base);
                int sid = (base + lane < end) ? (int)g_csr[base + lane] : 0;
                for (int t = 0; t < n; ++t) {
                    int s = __shfl_sync(0xffffffffu, sid, t);
                    uint2 raw = g_hA[(long)s * 32 + lane];
                    float2 f0 = __half22float2(*(__half2*)&raw.x);
                    float2 f1 = __half22float2(*(__half2*)&raw.y);
                    lo.x += f0.x; lo.y += f0.y; hi.x += f1.x; hi.y += f1.y;
                }
            }
            float rin = g_rsi[d];
            float ro  = g_rso[d];
            float o0 = fmaxf(lo.x * rin + blo.x, 0.f) * ro;
            float o1 = fmaxf(lo.y * rin + blo.y, 0.f) * ro;
            float o2 = fmaxf(hi.x * rin + bhi.x, 0.f) * ro;
            float o3 = fmaxf(hi.y * rin + bhi.y, 0.f) * ro;
            pp0[j] = pack2(o0, o2);
            pp1[j] = pack2(o1, o3);
        }
        unsigned long long ay[4][2];
#pragma unroll
        for (int j = 0; j < 4; ++j) { ay[j][0] = 0ull; ay[j][1] = 0ull; }
#pragma unroll 2
        for (int g = 0; g < 32; ++g) {
            unsigned long long wa0 = sW2p[(2 * g) * 64 + lane];
            unsigned long long wb0 = sW2p[(2 * g) * 64 + 32 + lane];
            unsigned long long wa1 = sW2p[(2 * g + 1) * 64 + lane];
            unsigned long long wb1 = sW2p[(2 * g + 1) * 64 + 32 + lane];
#pragma unroll
            for (int j = 0; j < 4; ++j) {
                unsigned long long c0 = __shfl_sync(0xffffffffu, pp0[j], g);
                ffma2(ay[j][0], c0, wa0); ffma2(ay[j][1], c0, wb0);
                unsigned long long c1 = __shfl_sync(0xffffffffu, pp1[j], g);
                ffma2(ay[j][0], c1, wa1); ffma2(ay[j][1], c1, wb1);
            }
        }
#pragma unroll
        for (int j = 0; j < 4; ++j) {
            int d = b * 4 + j;
            float2 v0 = unpack2(ay[j][0]);
            float2 v1 = unpack2(ay[j][1]);
            __half* yr = g_yh + (long)d * CLS;
            yr[lane] = __float2half_rn(v0.x + v0.y);
            if (lane < 8) yr[32 + lane] = __float2half_rn(v1.x + v1.y);
        }
    }
}

// Layer-2 aggregation: lane<20 owns uint pair (cols 2l,2l+1).
// out = rsi * sum yh[src] + b2   (fp32 accum)
__global__ __launch_bounds__(256) void k_spmm2(const float* __restrict__ b2,
                                               float* __restrict__ out) {
    int warp = threadIdx.x >> 5, lane = threadIdx.x & 31;
    int d = blockIdx.x * 8 + warp;
    if (d >= NN) return;
    int beg = g_off[d], end = g_off[d + 1];
    float ax = 0.f, ay = 0.f;
    for (int base = beg; base < end; base += 32) {
        int n = min(32, end - base);
        int sid = (base + lane < end) ? (int)g_csr[base + lane] : 0;
        for (int t = 0; t < n; ++t) {
            int s = __shfl_sync(0xffffffffu, sid, t);
            if (lane < 20) {
                unsigned u = ((const unsigned*)(g_yh + (long)s * CLS))[lane];
                float2 f = __half22float2(*(__half2*)&u);
                ax += f.x; ay += f.y;
            }
        }
    }
    if (lane < 20) {
        float rin = g_rsi[d];
        float2 bp = ((const float2*)b2)[lane];
        ((float2*)(out + (long)d * CLS))[lane] =
            make_float2(ax * rin + bp.x, ay * rin + bp.y);
    }
}

extern "C" void kernel_launch(void* const* d_in, const int* in_sizes, int n_in,
                              void* d_out, int out_size) {
    const int*   feat = (const int*)  d_in[0];
    const int*   src  = (const int*)  d_in[1];
    const int*   dst  = (const int*)  d_in[2];
    const float* emb  = (const float*)d_in[3];
    const float* W1   = (const float*)d_in[4];
    const float* b1   = (const float*)d_in[5];
    const float* W2   = (const float*)d_in[6];
    const float* b2   = (const float*)d_in[7];
    float* out = (float*)d_out;

    const int smemT = 64 * 128 * 8;   // 64KB
    cudaFuncSetAttribute(k_tabledeg,
                         cudaFuncAttributeMaxDynamicSharedMemorySize, smemT);

    k_zero<<<NB, 256>>>();
    k_tabledeg<<<GEMMB + DEGB, 256, smemT>>>(emb, W1, src, dst);
    k_scan<<<NB, 256>>>();
    k_fillembed<<<EMBB + DEGB, 256>>>(feat, src, dst);
    k_layer1<<<592, 256>>>(b1, W2);
    k_spmm2<<<NN / 8, 256>>>(b2, out);
}

// round 9
// speedup vs baseline: 4.4020x; 1.0215x over previous
#include <cuda_runtime.h>
#include <cuda_fp16.h>

// GCN: embedding mean-pool -> GraphConv(128->128, relu) -> GraphConv(128->40)
// embT = emb@W1 reorder; pull-based CSR (uint16); fp16 CG staging.
// R9: MLP-4 unrolled gathers (latency-bound fix per R8 ncu: issue=49%,
// no throughput ceiling hit). Embed preloads all 20 rows before reducing.

#define NN   50000
#define NE   800000
#define FD   128
#define SEQ  20
#define CLS  40
#define VOC  32000
#define NB   ((NN + 255) / 256)      // 196
#define GEMMB 296
#define DEGB  ((NE + 255) / 256)     // 3125
#define EMBB  (NN / 8)               // 6250

static __device__ uint2 g_embT[(size_t)VOC * 32];   // emb@W1, fp16 CG layout
static __device__ uint2 g_hA[(size_t)NN * 32];      // pooled feats, fp16 CG
static __device__ __half g_yh[(size_t)NN * CLS];
static __device__ int   g_odeg[NN];
static __device__ int   g_ideg[NN];
static __device__ float g_rso[NN];
static __device__ float g_rsi[NN];
static __device__ int   g_off[NN + 1];
static __device__ int   g_cur[NN];
static __device__ unsigned short g_csr[NE];
static __device__ int   g_btot[256];
static __device__ int   g_arrive;

__device__ __forceinline__ unsigned long long pack2(float lo, float hi) {
    unsigned long long r;
    asm("mov.b64 %0, {%1, %2};" : "=l"(r) : "f"(lo), "f"(hi));
    return r;
}
__device__ __forceinline__ float2 unpack2(unsigned long long v) {
    float lo, hi;
    asm("mov.b64 {%0, %1}, %2;" : "=f"(lo), "=f"(hi) : "l"(v));
    return make_float2(lo, hi);
}
__device__ __forceinline__ void ffma2(unsigned long long& d,
                                      unsigned long long a,
                                      unsigned long long b) {
    asm("fma.rn.f32x2 %0, %1, %2, %0;" : "+l"(d) : "l"(a), "l"(b));
}
__device__ __forceinline__ void acc_cg(float2& lo, float2& hi, uint2 raw) {
    float2 f0 = __half22float2(*(__half2*)&raw.x);
    float2 f1 = __half22float2(*(__half2*)&raw.y);
    lo.x += f0.x; lo.y += f0.y; hi.x += f1.x; hi.y += f1.y;
}

__global__ __launch_bounds__(256) void k_zero() {
    int i = blockIdx.x * 256 + threadIdx.x;
    if (i < NN) { g_odeg[i] = 0; g_ideg[i] = 0; g_cur[i] = 0; }
    if (i == 0) g_arrive = 0;
}

// blocks [0,GEMMB): embT = emb @ W1 -> fp16 CG (W1 k-half pairs in smem)
// blocks [GEMMB, GEMMB+DEGB): degree atomics (one pass over edges)
__global__ __launch_bounds__(256) void k_tabledeg(const float* __restrict__ emb,
                                                  const float* __restrict__ W1,
                                                  const int* __restrict__ src,
                                                  const int* __restrict__ dst) {
    if (blockIdx.x >= GEMMB) {
        int e = (blockIdx.x - GEMMB) * 256 + threadIdx.x;
        if (e < NE) {
            atomicAdd(&g_odeg[src[e]], 1);
            atomicAdd(&g_ideg[dst[e]], 1);
        }
        return;
    }
    extern __shared__ unsigned long long sW1p[];      // 64*128 u64 = 64KB
    for (int i = threadIdx.x; i < 64 * 128; i += 256) {
        int kp = i >> 7, c = i & 127;
        sW1p[i] = pack2(W1[kp * FD + c], W1[(kp + 64) * FD + c]);
    }
    __syncthreads();
    int warp = threadIdx.x >> 5, lane = threadIdx.x & 31;
    const int nwarps = GEMMB * 8;
    for (int b = blockIdx.x * 8 + warp; b < VOC / 4; b += nwarps) {
        unsigned long long px0[4], px1[4];
#pragma unroll
        for (int j = 0; j < 4; ++j) {
            int v = b * 4 + j;
            const float* row = emb + (long)v * FD;
            float2 a = *(const float2*)(row + 2 * lane);
            float2 c = *(const float2*)(row + 64 + 2 * lane);
            px0[j] = pack2(a.x, c.x);
            px1[j] = pack2(a.y, c.y);
        }
        unsigned long long acc[4][4];
#pragma unroll
        for (int j = 0; j < 4; ++j)
#pragma unroll
            for (int c = 0; c < 4; ++c) acc[j][c] = 0ull;
#pragma unroll 2
        for (int g = 0; g < 32; ++g) {
            const ulonglong2* w0 = (const ulonglong2*)&sW1p[(2 * g) * FD];
            const ulonglong2* w1 = (const ulonglong2*)&sW1p[(2 * g + 1) * FD];
            ulonglong2 wlo0 = w0[lane], whi0 = w0[32 + lane];
            ulonglong2 wlo1 = w1[lane], whi1 = w1[32 + lane];
#pragma unroll
            for (int j = 0; j < 4; ++j) {
                unsigned long long b0 = __shfl_sync(0xffffffffu, px0[j], g);
                ffma2(acc[j][0], b0, wlo0.x); ffma2(acc[j][1], b0, wlo0.y);
                ffma2(acc[j][2], b0, whi0.x); ffma2(acc[j][3], b0, whi0.y);
                unsigned long long b1v = __shfl_sync(0xffffffffu, px1[j], g);
                ffma2(acc[j][0], b1v, wlo1.x); ffma2(acc[j][1], b1v, wlo1.y);
                ffma2(acc[j][2], b1v, whi1.x); ffma2(acc[j][3], b1v, whi1.y);
            }
        }
#pragma unroll
        for (int j = 0; j < 4; ++j) {
            int v = b * 4 + j;
            float2 u0 = unpack2(acc[j][0]), u1 = unpack2(acc[j][1]);
            float2 u2 = unpack2(acc[j][2]), u3 = unpack2(acc[j][3]);
            __half2 h01 = __floats2half2_rn(u0.x + u0.y, u1.x + u1.y);
            __half2 h23 = __floats2half2_rn(u2.x + u2.y, u3.x + u3.y);
            uint2 o;
            o.x = *(unsigned*)&h01;
            o.y = *(unsigned*)&h23;
            g_embT[(long)v * 32 + lane] = o;
        }
    }
}

// Single-launch exclusive scan of g_ideg -> g_off, plus rso/rsi.
// All NB=196 blocks co-resident (196 < 148*8) -> spin barrier safe.
__global__ __launch_bounds__(256) void k_scan() {
    __shared__ int s[256];
    int tid = threadIdx.x;
    int i = blockIdx.x * 256 + tid;
    int v = (i < NN) ? g_ideg[i] : 0;
    s[tid] = v; __syncthreads();
#pragma unroll
    for (int st = 1; st < 256; st <<= 1) {
        int t = (tid >= st) ? s[tid - st] : 0;
        __syncthreads();
        s[tid] += t;
        __syncthreads();
    }
    int local_ex = s[tid] - v;
    if (tid == 255) g_btot[blockIdx.x] = s[255];
    __syncthreads();
    if (tid == 0) {
        __threadfence();
        atomicAdd(&g_arrive, 1);
        while (atomicAdd(&g_arrive, 0) < (int)gridDim.x) {}
        __threadfence();
    }
    __syncthreads();
    int pv = (tid < (int)blockIdx.x) ? g_btot[tid] : 0;
    s[tid] = pv; __syncthreads();
#pragma unroll
    for (int st = 128; st > 0; st >>= 1) {
        if (tid < st) s[tid] += s[tid + st];
        __syncthreads();
    }
    int prefix = s[0];
    if (i < NN) {
        g_off[i] = local_ex + prefix;
        g_rso[i] = rsqrtf((float)max(g_odeg[i], 1));
        g_rsi[i] = rsqrtf((float)max(g_ideg[i], 1));
    }
    if (i == 0) g_off[NN] = NE;
}

// blocks [0,EMBB): warp per node. Preload ALL 20 embT rows (20 outstanding
// LDG.64s), then reduce -- latency-bound fix.
// blocks [EMBB, ...): CSR fill (uint16 src ids)
__global__ __launch_bounds__(256, 4) void k_fillembed(const int* __restrict__ feat,
                                                      const int* __restrict__ src,
                                                      const int* __restrict__ dst) {
    if (blockIdx.x >= EMBB) {
        int e = (blockIdx.x - EMBB) * 256 + threadIdx.x;
        if (e < NE) {
            int d = dst[e];
            int p = g_off[d] + atomicAdd(&g_cur[d], 1);
            g_csr[p] = (unsigned short)src[e];
        }
        return;
    }
    int w    = (blockIdx.x * 256 + threadIdx.x) >> 5;
    int lane = threadIdx.x & 31;
    int tok = 0;
    if (lane < SEQ) tok = feat[w * SEQ + lane];
    unsigned nzm = __ballot_sync(0xffffffffu, (lane < SEQ) && (tok != 0));
    float inv_cnt = 1.0f / (float)max(__popc(nzm), 1);
    uint2 rows[SEQ];
#pragma unroll
    for (int t = 0; t < SEQ; ++t) {
        int tk = __shfl_sync(0xffffffffu, tok, t);
        rows[t] = g_embT[(long)tk * 32 + lane];
    }
    float2 lo = make_float2(0.f, 0.f), hi = make_float2(0.f, 0.f);
#pragma unroll
    for (int t = 0; t < SEQ; ++t) acc_cg(lo, hi, rows[t]);
    float sc = g_rso[w] * inv_cnt;
    __half2 h01 = __floats2half2_rn(lo.x * sc, lo.y * sc);
    __half2 h23 = __floats2half2_rn(hi.x * sc, hi.y * sc);
    uint2 o;
    o.x = *(unsigned*)&h01;
    o.y = *(unsigned*)&h23;
    g_hA[(long)w * 32 + lane] = o;
}

// Layer1: warp handles 4 dst nodes. Gather with 4-way MLP unroll.
__global__ __launch_bounds__(256, 4) void k_layer1(const float* __restrict__ b1,
                                                   const float* __restrict__ W2) {
    __shared__ unsigned long long sW2p[64 * 64];      // 32KB
    for (int i = threadIdx.x; i < 64 * 64; i += 256) {
        int kp = i >> 6, c = i & 63;
        float lo = (c < CLS) ? W2[kp * CLS + c] : 0.f;
        float hi = (c < CLS) ? W2[(kp + 64) * CLS + c] : 0.f;
        sW2p[i] = pack2(lo, hi);
    }
    __syncthreads();
    int warp = threadIdx.x >> 5, lane = threadIdx.x & 31;
    float2 blo = ((const float2*)b1)[lane];
    float2 bhi = ((const float2*)(b1 + 64))[lane];
    int nwarps = gridDim.x * 8;
    for (int b = blockIdx.x * 8 + warp; b < NN / 4; b += nwarps) {
        unsigned long long pp0[4], pp1[4];
#pragma unroll
        for (int j = 0; j < 4; ++j) {
            int d = b * 4 + j;
            int beg = g_off[d], end = g_off[d + 1];
            float2 lo = make_float2(0.f, 0.f), hi = make_float2(0.f, 0.f);
            for (int base = beg; base < end; base += 32) {
                int n = min(32, end - base);
                int sid = (base + lane < end) ? (int)g_csr[base + lane] : 0;
                int t = 0;
                for (; t + 4 <= n; t += 4) {
                    int s0 = __shfl_sync(0xffffffffu, sid, t);
                    int s1 = __shfl_sync(0xffffffffu, sid, t + 1);
                    int s2 = __shfl_sync(0xffffffffu, sid, t + 2);
                    int s3 = __shfl_sync(0xffffffffu, sid, t + 3);
                    uint2 r0 = g_hA[(long)s0 * 32 + lane];
                    uint2 r1 = g_hA[(long)s1 * 32 + lane];
                    uint2 r2 = g_hA[(long)s2 * 32 + lane];
                    uint2 r3 = g_hA[(long)s3 * 32 + lane];
                    acc_cg(lo, hi, r0); acc_cg(lo, hi, r1);
                    acc_cg(lo, hi, r2); acc_cg(lo, hi, r3);
                }
                for (; t < n; ++t) {
                    int s = __shfl_sync(0xffffffffu, sid, t);
                    acc_cg(lo, hi, g_hA[(long)s * 32 + lane]);
                }
            }
            float rin = g_rsi[d];
            float ro  = g_rso[d];
            float o0 = fmaxf(lo.x * rin + blo.x, 0.f) * ro;
            float o1 = fmaxf(lo.y * rin + blo.y, 0.f) * ro;
            float o2 = fmaxf(hi.x * rin + bhi.x, 0.f) * ro;
            float o3 = fmaxf(hi.y * rin + bhi.y, 0.f) * ro;
            pp0[j] = pack2(o0, o2);
            pp1[j] = pack2(o1, o3);
        }
        unsigned long long ay[4][2];
#pragma unroll
        for (int j = 0; j < 4; ++j) { ay[j][0] = 0ull; ay[j][1] = 0ull; }
#pragma unroll 2
        for (int g = 0; g < 32; ++g) {
            unsigned long long wa0 = sW2p[(2 * g) * 64 + lane];
            unsigned long long wb0 = sW2p[(2 * g) * 64 + 32 + lane];
            unsigned long long wa1 = sW2p[(2 * g + 1) * 64 + lane];
            unsigned long long wb1 = sW2p[(2 * g + 1) * 64 + 32 + lane];
#pragma unroll
            for (int j = 0; j < 4; ++j) {
                unsigned long long c0 = __shfl_sync(0xffffffffu, pp0[j], g);
                ffma2(ay[j][0], c0, wa0); ffma2(ay[j][1], c0, wb0);
                unsigned long long c1 = __shfl_sync(0xffffffffu, pp1[j], g);
                ffma2(ay[j][0], c1, wa1); ffma2(ay[j][1], c1, wb1);
            }
        }
#pragma unroll
        for (int j = 0; j < 4; ++j) {
            int d = b * 4 + j;
            float2 v0 = unpack2(ay[j][0]);
            float2 v1 = unpack2(ay[j][1]);
            __half* yr = g_yh + (long)d * CLS;
            yr[lane] = __float2half_rn(v0.x + v0.y);
            if (lane < 8) yr[32 + lane] = __float2half_rn(v1.x + v1.y);
        }
    }
}

// Layer-2 aggregation with 4-way MLP unroll: lane<20 owns uint pair.
__global__ __launch_bounds__(256, 4) void k_spmm2(const float* __restrict__ b2,
                                                  float* __restrict__ out) {
    int warp = threadIdx.x >> 5, lane = threadIdx.x & 31;
    int d = blockIdx.x * 8 + warp;
    if (d >= NN) return;
    int beg = g_off[d], end = g_off[d + 1];
    float ax = 0.f, ay = 0.f;
    const unsigned* Y = (const unsigned*)g_yh;
    for (int base = beg; base < end; base += 32) {
        int n = min(32, end - base);
        int sid = (base + lane < end) ? (int)g_csr[base + lane] : 0;
        int t = 0;
        for (; t + 4 <= n; t += 4) {
            int s0 = __shfl_sync(0xffffffffu, sid, t);
            int s1 = __shfl_sync(0xffffffffu, sid, t + 1);
            int s2 = __shfl_sync(0xffffffffu, sid, t + 2);
            int s3 = __shfl_sync(0xffffffffu, sid, t + 3);
            if (lane < 20) {
                unsigned u0 = Y[s0 * 20 + lane];
                unsigned u1 = Y[s1 * 20 + lane];
                unsigned u2 = Y[s2 * 20 + lane];
                unsigned u3 = Y[s3 * 20 + lane];
                float2 f;
                f = __half22float2(*(__half2*)&u0); ax += f.x; ay += f.y;
                f = __half22float2(*(__half2*)&u1); ax += f.x; ay += f.y;
                f = __half22float2(*(__half2*)&u2); ax += f.x; ay += f.y;
                f = __half22float2(*(__half2*)&u3); ax += f.x; ay += f.y;
            }
        }
        for (; t < n; ++t) {
            int s = __shfl_sync(0xffffffffu, sid, t);
            if (lane < 20) {
                unsigned u = Y[s * 20 + lane];
                float2 f = __half22float2(*(__half2*)&u);
                ax += f.x; ay += f.y;
            }
        }
    }
    if (lane < 20) {
        float rin = g_rsi[d];
        float2 bp = ((const float2*)b2)[lane];
        ((float2*)(out + (long)d * CLS))[lane] =
            make_float2(ax * rin + bp.x, ay * rin + bp.y);
    }
}

extern "C" void kernel_launch(void* const* d_in, const int* in_sizes, int n_in,
                              void* d_out, int out_size) {
    const int*   feat = (const int*)  d_in[0];
    const int*   src  = (const int*)  d_in[1];
    const int*   dst  = (const int*)  d_in[2];
    const float* emb  = (const float*)d_in[3];
    const float* W1   = (const float*)d_in[4];
    const float* b1   = (const float*)d_in[5];
    const float* W2   = (const float*)d_in[6];
    const float* b2   = (const float*)d_in[7];
    float* out = (float*)d_out;

    const int smemT = 64 * 128 * 8;   // 64KB
    cudaFuncSetAttribute(k_tabledeg,
                         cudaFuncAttributeMaxDynamicSharedMemorySize, smemT);

    k_zero<<<NB, 256>>>();
    k_tabledeg<<<GEMMB + DEGB, 256, smemT>>>(emb, W1, src, dst);
    k_scan<<<NB, 256>>>();
    k_fillembed<<<EMBB + DEGB, 256>>>(feat, src, dst);
    k_layer1<<<592, 256>>>(b1, W2);
    k_spmm2<<<NN / 8, 256>>>(b2, out);
}